// round 8
// baseline (speedup 1.0000x reference)
#include <cuda_runtime.h>
#include <math.h>
#include <cstdint>

#define TT 1024
#define CC 1024
#define EE 8
#define NT 4096   // B*T tokens
#define NR 8192   // 2 slots * NT rows
#define MEG 1048576

// ---------------- scratch (device globals; no allocs allowed) ----------------
__device__ float g_kv[(size_t)2 * NT * CC];       // [k(perm,rounded) | v(plain)]
__device__ float g_vT[(size_t)64 * 64 * TT];      // [b*16+h][d][t perm8], rounded
__device__ float g_q [(size_t)NR * CC];           // perm8 cols, rounded
__device__ float g_at[(size_t)NR * CC];           // perm8 cols, rounded
__device__ float g_o [(size_t)NR * CC];           // plain
__device__ float g_xp[(size_t)NT * CC];           // x, perm8 cols, rounded
__device__ float g_wp[(size_t)18 * MEG];          // prepped weights [k8][n][t][p]
__device__ float g_w [NR];
__device__ int   g_rl[EE][NT];
__device__ int   g_cnt[EE];

__global__ void zero_cnt() { if (threadIdx.x < EE) g_cnt[threadIdx.x] = 0; }

// ---------------- helpers ----------------
__device__ __forceinline__ uint32_t smem_u32(const void* p) {
    uint32_t a;
    asm("{ .reg .u64 t; cvta.to.shared.u64 t, %1; cvt.u32.u64 %0, t; }" : "=r"(a) : "l"(p));
    return a;
}
__device__ __forceinline__ uint32_t f2tf32(float x) {
    uint32_t u;
    asm("cvt.rna.tf32.f32 %0, %1;" : "=r"(u) : "f"(x));
    return u;
}
__device__ __forceinline__ float roundtf(float x) { return __uint_as_float(f2tf32(x)); }
__device__ __forceinline__ int perm8(int c) {
    return (c & ~7) | ((c & 3) << 1) | ((c >> 2) & 1);
}
__device__ __forceinline__ void mma_tf32(float* d, const uint32_t* a, const uint32_t* b) {
    asm volatile(
        "mma.sync.aligned.m16n8k8.row.col.f32.tf32.tf32.f32 "
        "{%0,%1,%2,%3},{%4,%5,%6,%7},{%8,%9},{%0,%1,%2,%3};"
        : "+f"(d[0]), "+f"(d[1]), "+f"(d[2]), "+f"(d[3])
        : "r"(a[0]), "r"(a[1]), "r"(a[2]), "r"(a[3]), "r"(b[0]), "r"(b[1]));
}
__device__ __forceinline__ void cp16(uint32_t dst, const void* src) {
    asm volatile("cp.async.ca.shared.global [%0], [%1], 16;" :: "r"(dst), "l"(src) : "memory");
}
#define CP_COMMIT() asm volatile("cp.async.commit_group;" ::: "memory")
#define CP_WAIT0()  asm volatile("cp.async.wait_group 0;" ::: "memory")
#define CP_WAIT1()  asm volatile("cp.async.wait_group 1;" ::: "memory")

// ---------------- gating ----------------
__global__ __launch_bounds__(256) void gate_kernel(
    const float* __restrict__ x, const float* __restrict__ noise,
    const float* __restrict__ Wg, const float* __restrict__ Wn)
{
    int row = blockIdx.x;
    int tid = threadIdx.x;
    const float* xr = x + (size_t)row * CC;

    float accg[8], accn[8];
#pragma unroll
    for (int e = 0; e < 8; e++) { accg[e] = 0.f; accn[e] = 0.f; }
    for (int c = tid; c < CC; c += 256) {
        float xv = xr[c];
        const float* wg = Wg + c * 8;
        const float* wn = Wn + c * 8;
#pragma unroll
        for (int e = 0; e < 8; e++) { accg[e] += xv * wg[e]; accn[e] += xv * wn[e]; }
    }
    __shared__ float red[16][256];
#pragma unroll
    for (int e = 0; e < 8; e++) { red[e][tid] = accg[e]; red[8 + e][tid] = accn[e]; }
    __syncthreads();
    __shared__ float fin[16];
    if (tid < 16) {
        float s = 0.f;
        for (int i = 0; i < 256; i++) s += red[tid][i];
        fin[tid] = s;
    }
    __syncthreads();
    if (tid == 0) {
        float logit[8];
#pragma unroll
        for (int e = 0; e < 8; e++) {
            float z  = fin[8 + e];
            float sp = (z > 20.f) ? z : log1pf(expf(z));
            logit[e] = fin[e] + noise[row * 8 + e] * sp;
        }
        int i0 = 0; float v0 = logit[0];
#pragma unroll
        for (int e = 1; e < 8; e++) if (logit[e] > v0) { v0 = logit[e]; i0 = e; }
        int i1 = -1; float v1 = -INFINITY;
#pragma unroll
        for (int e = 0; e < 8; e++) if (e != i0 && logit[e] > v1) { v1 = logit[e]; i1 = e; }
        float p1 = 1.f / (1.f + expf(v0 - v1));
        float p0 = 1.f - p1;
        g_w[row]      = p0;
        g_w[NT + row] = p1;
        int pos0 = atomicAdd(&g_cnt[i0], 1); g_rl[i0][pos0] = row;
        int pos1 = atomicAdd(&g_cnt[i1], 1); g_rl[i1][pos1] = NT + row;
    }
}

// ---------------- x -> rounded + perm8 ----------------
// each thread handles one 8-col group
__global__ void round_permute_x(const float* __restrict__ x)
{
    int i = blockIdx.x * 256 + threadIdx.x;          // group id
    const float* src = x + (size_t)i * 8;
    float4 a = *(const float4*)src;
    float4 b = *(const float4*)(src + 4);
    float4 o0 = make_float4(roundtf(a.x), roundtf(b.x), roundtf(a.y), roundtf(b.y));
    float4 o1 = make_float4(roundtf(a.z), roundtf(b.z), roundtf(a.w), roundtf(b.w));
    float* dst = g_xp + (size_t)i * 8;
    *(float4*)dst = o0;
    *(float4*)(dst + 4) = o1;
}

// ---------------- weight prep: round + interleave [k8][n][t][p] ----------------
// z: 0=Wk, 1=Wv, 2..9=Wq[e], 10..17=Wo[e]
__global__ __launch_bounds__(256) void prep_w(
    const float* __restrict__ Wk, const float* __restrict__ Wv,
    const float* __restrict__ Wq, const float* __restrict__ Wo)
{
    int z = blockIdx.z;
    const float* src = (z == 0) ? Wk : (z == 1) ? Wv :
                       (z < 10) ? Wq + (size_t)(z - 2) * MEG : Wo + (size_t)(z - 10) * MEG;
    float* dst = g_wp + (size_t)z * MEG;
    int k8 = blockIdx.y;
    int n  = blockIdx.x * 256 + threadIdx.x;
    float v[8];
#pragma unroll
    for (int t = 0; t < 8; t++) v[t] = src[(size_t)(k8 * 8 + t) * CC + n];
    float4 o0 = make_float4(roundtf(v[0]), roundtf(v[4]), roundtf(v[1]), roundtf(v[5]));
    float4 o1 = make_float4(roundtf(v[2]), roundtf(v[6]), roundtf(v[3]), roundtf(v[7]));
    float* d = dst + ((size_t)k8 * 1024 + n) * 8;
    *(float4*)d = o0;
    *(float4*)(d + 4) = o1;
}

// ---------------- V transpose per (b,h): [t][d] -> [d][perm8(t)], rounded ----------------
__global__ __launch_bounds__(256) void transpose_v()
{
    __shared__ float tile[32][33];
    int bh = blockIdx.z;
    int b = bh >> 4, h = bh & 15;
    int t0 = blockIdx.x * 32, d0 = blockIdx.y * 32;
    int tx = threadIdx.x & 31, ty = threadIdx.x >> 5;
    const float* src = g_kv + (size_t)NT * CC;
#pragma unroll
    for (int r = 0; r < 4; r++) {
        int tt = t0 + ty + r * 8;
        tile[ty + r * 8][tx] = src[(size_t)(b * TT + tt) * CC + h * 64 + d0 + tx];
    }
    __syncthreads();
#pragma unroll
    for (int r = 0; r < 4; r++) {
        int dd = d0 + ty + r * 8;
        g_vT[((size_t)bh * 64 + dd) * TT + perm8(t0 + tx)] = roundtf(tile[tx][ty + r * 8]);
    }
}

// ---------------- tf32 mma GEMM, cp.async 3-stage, pair-permuted fragments ----------------
// A (g_xp/g_at) has perm8 cols; B = g_wp slab. mode 3: dense k/v fused.
// mode 1: gather token rows. mode 2: gather direct rows.
#define AST 40
#define GS_A (128 * AST)   // floats per stage
#define GS_B (4 * 1024)
__global__ __launch_bounds__(128) void gemm_mma(
    const float* __restrict__ A, const float* __restrict__ Bp,
    float* __restrict__ C, int mode)
{
    extern __shared__ float smg[];
    float* As = smg;                 // [3][128][40]
    float* Bs = smg + 3 * GS_A;      // [3][4][1024]
    __shared__ int s_src[128];
    __shared__ int s_dst[128];

    int tid = threadIdx.x, lane = tid & 31, wid = tid >> 5;
    int z = blockIdx.z, row0 = blockIdx.y * 128, n0 = blockIdx.x * 128;

    const float* Wb;
    float* Cout = C;
    int cnt = NT;
    int prm;                          // permute+round output?
    if (mode == 3) {
        Wb = g_wp + (size_t)z * MEG;
        Cout = C + (size_t)z * NT * CC;
        prm = (z == 0);
    } else {
        Wb = Bp + (size_t)z * MEG;
        cnt = g_cnt[z];
        if (row0 >= cnt) return;
        prm = (mode == 1);
    }
    {
        int gr = row0 + tid;
        if (mode == 3) { s_src[tid] = gr; s_dst[tid] = gr; }
        else if (gr < cnt) {
            int r = g_rl[z][gr];
            s_src[tid] = (mode == 1) ? (r & (NT - 1)) : r;
            s_dst[tid] = r;
        } else { s_src[tid] = 0; s_dst[tid] = -1; }
    }
    __syncthreads();

    uint32_t sbA = smem_u32(As);
    uint32_t sbB = smem_u32(Bs);
    // A staging: 1024 cp16/chunk; thread does 8: lin = tid + j*128, r=lin>>3, g=lin&7
    const float* aptr[8];
    uint32_t adst[8];
#pragma unroll
    for (int j = 0; j < 8; j++) {
        int lin = tid + j * 128;
        int r = lin >> 3, g = lin & 7;
        aptr[j] = A + (size_t)s_src[r] * CC + g * 4;
        adst[j] = sbA + (uint32_t)(r * AST + g * 4) * 4;
    }
    // B staging: 1024 cp16/chunk: lin: k8l = lin>>8, q = lin&255
    const float* bbase = Wb + (size_t)n0 * 8;

    auto issue = [&](int c, int stg) {
        uint32_t ao = (uint32_t)stg * GS_A * 4;
        uint32_t bo = (uint32_t)stg * GS_B * 4;
#pragma unroll
        for (int j = 0; j < 8; j++) cp16(adst[j] + ao, aptr[j] + c * 32);
#pragma unroll
        for (int j = 0; j < 8; j++) {
            int lin = tid + j * 128;
            int k8l = lin >> 8, q = lin & 255;
            cp16(sbB + bo + (uint32_t)(k8l * 1024 + q * 4) * 4,
                 bbase + (size_t)(4 * c + k8l) * 8192 + q * 4);
        }
        CP_COMMIT();
    };

    float acc[4][8][4];
#pragma unroll
    for (int mt = 0; mt < 4; mt++)
#pragma unroll
        for (int nt = 0; nt < 8; nt++)
#pragma unroll
            for (int q = 0; q < 4; q++) acc[mt][nt][q] = 0.f;

    int wm = (wid >> 1) * 64;
    int wn = (wid & 1) * 64;

    issue(0, 0); issue(1, 1);
#pragma unroll 1
    for (int c = 0; c < 32; c++) {
        int stg = c % 3;
        CP_WAIT1();
        __syncthreads();
        if (c + 2 < 32) issue(c + 2, (c + 2) % 3);
        const float* Ab = As + stg * GS_A;
        const float* Bb = Bs + stg * GS_B;
#pragma unroll
        for (int k8 = 0; k8 < 4; k8++) {
            int kcol = k8 * 8 + (lane & 3) * 2;
            uint32_t af[4][4];
#pragma unroll
            for (int mt = 0; mt < 4; mt++) {
                int r = wm + mt * 16 + (lane >> 2);
                float2 lo = *(const float2*)(Ab + r * AST + kcol);
                float2 hi = *(const float2*)(Ab + (r + 8) * AST + kcol);
                af[mt][0] = __float_as_uint(lo.x); af[mt][1] = __float_as_uint(hi.x);
                af[mt][2] = __float_as_uint(lo.y); af[mt][3] = __float_as_uint(hi.y);
            }
#pragma unroll
            for (int nt = 0; nt < 8; nt++) {
                int n = wn + nt * 8 + (lane >> 2);
                float2 bv = *(const float2*)(Bb + k8 * 1024 + n * 8 + (lane & 3) * 2);
                uint32_t bf[2] = { __float_as_uint(bv.x), __float_as_uint(bv.y) };
#pragma unroll
                for (int mt = 0; mt < 4; mt++)
                    mma_tf32(acc[mt][nt], af[mt], bf);
            }
        }
    }

    int r0 = wm + (lane >> 2);
    int cb = n0 + wn + (lane & 3) * 2;
#pragma unroll
    for (int mt = 0; mt < 4; mt++) {
        int dA = s_dst[r0 + mt * 16];
        int dB = s_dst[r0 + mt * 16 + 8];
#pragma unroll
        for (int nt = 0; nt < 8; nt++) {
            int gc = cb + nt * 8;
            if (prm) {
                int p0 = perm8(gc), p1 = perm8(gc + 1);
                if (dA >= 0) {
                    Cout[(size_t)dA * CC + p0] = roundtf(acc[mt][nt][0]);
                    Cout[(size_t)dA * CC + p1] = roundtf(acc[mt][nt][1]);
                }
                if (dB >= 0) {
                    Cout[(size_t)dB * CC + p0] = roundtf(acc[mt][nt][2]);
                    Cout[(size_t)dB * CC + p1] = roundtf(acc[mt][nt][3]);
                }
            } else {
                if (dA >= 0)
                    *(float2*)(Cout + (size_t)dA * CC + gc) = make_float2(acc[mt][nt][0], acc[mt][nt][1]);
                if (dB >= 0)
                    *(float2*)(Cout + (size_t)dB * CC + gc) = make_float2(acc[mt][nt][2], acc[mt][nt][3]);
            }
        }
    }
}

// ---------------- flash attention, tf32 mma, cp.async pipelined ----------------
// grid (8 qtiles, 16 heads, 8 = slot*4+b), 128 threads = 4 warps x 32 rows
#define QST 72
__global__ __launch_bounds__(128) void attn_mma()
{
    extern __shared__ float sm[];
    float* Qs = sm;                    // [128][72] perm8 d-cols
    float* Ks = sm + 128 * QST;        // [64][72]  perm8 d-cols
    float* Vt = Ks + 64 * QST;         // [64 d][72] perm8 j-cols
    float* Ps = Vt + 64 * QST;         // [128][72] perm8 j-cols

    int tid = threadIdx.x, lane = tid & 31, wid = tid >> 5;
    int qt = 7 - (int)blockIdx.x;
    int h  = blockIdx.y;
    int zb = blockIdx.z;
    int s = zb >> 2, b = zb & 3;
    int rbase = s * NT + b * TT;
    const float* qsrc  = g_q + (size_t)(rbase + qt * 128) * CC + h * 64;
    const float* ksrc  = g_kv + (size_t)(b * TT) * CC + h * 64;
    const float* vtsrc = g_vT + (size_t)(b * 16 + h) * 64 * TT;

    uint32_t sQ = smem_u32(Qs), sK = smem_u32(Ks), sV = smem_u32(Vt);

    auto issueK = [&](int kt) {
        const float* src = ksrc + (size_t)(kt * 64) * CC;
#pragma unroll
        for (int j = 0; j < 8; j++) {
            int lin = tid + j * 128;           // 1024 cp16
            int r = lin >> 4, g = lin & 15;
            cp16(sK + (uint32_t)(r * QST + g * 4) * 4, src + (size_t)r * CC + g * 4);
        }
        CP_COMMIT();
    };
    auto issueV = [&](int kt) {
#pragma unroll
        for (int j = 0; j < 8; j++) {
            int lin = tid + j * 128;
            int d = lin >> 4, g = lin & 15;
            cp16(sV + (uint32_t)(d * QST + g * 4) * 4,
                 vtsrc + (size_t)d * TT + kt * 64 + g * 4);
        }
        CP_COMMIT();
    };

    // prologue: stage Q + K0 in one group
    {
#pragma unroll
        for (int j = 0; j < 16; j++) {
            int lin = tid + j * 128;           // 2048 cp16
            int r = lin >> 4, g = lin & 15;
            cp16(sQ + (uint32_t)(r * QST + g * 4) * 4, qsrc + (size_t)r * CC + g * 4);
        }
        issueK(0);                             // commits Q+K together
    }

    float Oa[2][8][4];
    float mrow[4], lrow[4];
#pragma unroll
    for (int mt = 0; mt < 2; mt++)
#pragma unroll
        for (int nt = 0; nt < 8; nt++)
#pragma unroll
            for (int q = 0; q < 4; q++) Oa[mt][nt][q] = 0.f;
#pragma unroll
    for (int i = 0; i < 4; i++) { mrow[i] = -1e30f; lrow[i] = 0.f; }

    int ktmax = 2 * qt + 1;
#pragma unroll 1
    for (int kt = 0; kt <= ktmax; kt++) {
        CP_WAIT0();            // K(kt) landed
        __syncthreads();       // all warps past previous PV (Vt free)
        issueV(kt);

        // S = Q @ K^T
        float sa[2][8][4];
#pragma unroll
        for (int mt = 0; mt < 2; mt++)
#pragma unroll
            for (int nt = 0; nt < 8; nt++)
#pragma unroll
                for (int q = 0; q < 4; q++) sa[mt][nt][q] = 0.f;
#pragma unroll
        for (int k8 = 0; k8 < 8; k8++) {
            int kcol = k8 * 8 + (lane & 3) * 2;
            uint32_t af[2][4];
#pragma unroll
            for (int mt = 0; mt < 2; mt++) {
                int r = wid * 32 + mt * 16 + (lane >> 2);
                float2 lo = *(const float2*)(Qs + r * QST + kcol);
                float2 hi = *(const float2*)(Qs + (r + 8) * QST + kcol);
                af[mt][0] = __float_as_uint(lo.x); af[mt][1] = __float_as_uint(hi.x);
                af[mt][2] = __float_as_uint(lo.y); af[mt][3] = __float_as_uint(hi.y);
            }
#pragma unroll
            for (int nt = 0; nt < 8; nt++) {
                int n = nt * 8 + (lane >> 2);
                float2 bv = *(const float2*)(Ks + n * QST + kcol);
                uint32_t bf[2] = { __float_as_uint(bv.x), __float_as_uint(bv.y) };
#pragma unroll
                for (int mt = 0; mt < 2; mt++)
                    mma_tf32(sa[mt][nt], af[mt], bf);
            }
        }

        // online softmax + P store (perm8 cols, rounded)
        bool domask = (kt >= 2 * qt);
#pragma unroll
        for (int mt = 0; mt < 2; mt++) {
            int rl = wid * 32 + mt * 16 + (lane >> 2);
#pragma unroll
            for (int half = 0; half < 2; half++) {
                int mi = mt * 2 + half;
                int ig = qt * 128 + rl + half * 8;
                float v[16];
#pragma unroll
                for (int nt = 0; nt < 8; nt++) {
                    float s0 = sa[mt][nt][half * 2 + 0] * 0.125f;
                    float s1 = sa[mt][nt][half * 2 + 1] * 0.125f;
                    if (domask) {
                        int jg = kt * 64 + nt * 8 + 2 * (lane & 3);
                        if (jg > ig)     s0 = -1e30f;
                        if (jg + 1 > ig) s1 = -1e30f;
                    }
                    v[nt * 2] = s0; v[nt * 2 + 1] = s1;
                }
                float rm = v[0];
#pragma unroll
                for (int j = 1; j < 16; j++) rm = fmaxf(rm, v[j]);
                rm = fmaxf(rm, __shfl_xor_sync(0xFFFFFFFFu, rm, 1));
                rm = fmaxf(rm, __shfl_xor_sync(0xFFFFFFFFu, rm, 2));
                float mn = fmaxf(mrow[mi], rm);
                float alpha = __expf(mrow[mi] - mn);
                float rs = 0.f;
#pragma unroll
                for (int j = 0; j < 16; j++) { float p = __expf(v[j] - mn); v[j] = p; rs += p; }
                rs += __shfl_xor_sync(0xFFFFFFFFu, rs, 1);
                rs += __shfl_xor_sync(0xFFFFFFFFu, rs, 2);
                mrow[mi] = mn;
                lrow[mi] = lrow[mi] * alpha + rs;
#pragma unroll
                for (int nt = 0; nt < 8; nt++) {
                    Oa[mt][nt][half * 2 + 0] *= alpha;
                    Oa[mt][nt][half * 2 + 1] *= alpha;
                }
                int prow = rl + half * 8;
                float* pr = Ps + prow * QST;
#pragma unroll
                for (int nt = 0; nt < 8; nt++) {
                    int j0 = nt * 8 + 2 * (lane & 3);
                    pr[perm8(j0)]     = roundtf(v[nt * 2]);
                    pr[perm8(j0 + 1)] = roundtf(v[nt * 2 + 1]);
                }
            }
        }
        __syncwarp();

        CP_WAIT0();            // V(kt) landed
        __syncthreads();       // all warps done reading Ks
        if (kt < ktmax) issueK(kt + 1);

        // O += P @ V
#pragma unroll
        for (int k8 = 0; k8 < 8; k8++) {
            int kcol = k8 * 8 + (lane & 3) * 2;
            uint32_t af[2][4];
#pragma unroll
            for (int mt = 0; mt < 2; mt++) {
                int r = wid * 32 + mt * 16 + (lane >> 2);
                float2 lo = *(const float2*)(Ps + r * QST + kcol);
                float2 hi = *(const float2*)(Ps + (r + 8) * QST + kcol);
                af[mt][0] = __float_as_uint(lo.x); af[mt][1] = __float_as_uint(hi.x);
                af[mt][2] = __float_as_uint(lo.y); af[mt][3] = __float_as_uint(hi.y);
            }
#pragma unroll
            for (int nt = 0; nt < 8; nt++) {
                int n = nt * 8 + (lane >> 2);
                float2 bv = *(const float2*)(Vt + n * QST + kcol);
                uint32_t bf[2] = { __float_as_uint(bv.x), __float_as_uint(bv.y) };
#pragma unroll
                for (int mt = 0; mt < 2; mt++)
                    mma_tf32(Oa[mt][nt], af[mt], bf);
            }
        }
    }

    // write O: perm8 cols + rounded (pre-rounds the o-GEMM A operand)
#pragma unroll
    for (int mt = 0; mt < 2; mt++) {
        int rl = wid * 32 + mt * 16 + (lane >> 2);
#pragma unroll
        for (int half = 0; half < 2; half++) {
            int mi = mt * 2 + half;
            float inv = 1.f / lrow[mi];
            float* orow = g_at + (size_t)(rbase + qt * 128 + rl + half * 8) * CC;
#pragma unroll
            for (int nt = 0; nt < 8; nt++) {
                int c0 = h * 64 + nt * 8 + 2 * (lane & 3);
                orow[perm8(c0)]     = roundtf(Oa[mt][nt][half * 2 + 0] * inv);
                orow[perm8(c0 + 1)] = roundtf(Oa[mt][nt][half * 2 + 1] * inv);
            }
        }
    }
}

// ---------------- final combine ----------------
__global__ void combine(float* __restrict__ out)
{
    int i = blockIdx.x * 256 + threadIdx.x;
    int token = i >> 10;
    out[i] = g_w[token] * g_o[i] + g_w[NT + token] * g_o[(size_t)NT * CC + i];
}

// ---------------- launch ----------------
extern "C" void kernel_launch(void* const* d_in, const int* in_sizes, int n_in,
                              void* d_out, int out_size)
{
    const float* x     = (const float*)d_in[0];
    const float* noise = (const float*)d_in[1];
    const float* Wk    = (const float*)d_in[2];
    const float* Wv    = (const float*)d_in[3];
    const float* Wq    = (const float*)d_in[4];
    const float* Wo    = (const float*)d_in[5];
    const float* Wg    = (const float*)d_in[6];
    const float* Wn    = (const float*)d_in[7];
    float* out = (float*)d_out;

    float *pkv, *pq, *pat, *po, *pxp, *pwp;
    cudaGetSymbolAddress((void**)&pkv, g_kv);
    cudaGetSymbolAddress((void**)&pq,  g_q);
    cudaGetSymbolAddress((void**)&pat, g_at);
    cudaGetSymbolAddress((void**)&po,  g_o);
    cudaGetSymbolAddress((void**)&pxp, g_xp);
    cudaGetSymbolAddress((void**)&pwp, g_wp);

    const int gemm_smem = (3 * GS_A + 3 * GS_B) * 4;      // 110592
    const int attn_smem = (128 + 64 + 64 + 128) * QST * 4; // 110592
    cudaFuncSetAttribute(gemm_mma, cudaFuncAttributeMaxDynamicSharedMemorySize, gemm_smem);
    cudaFuncSetAttribute(attn_mma, cudaFuncAttributeMaxDynamicSharedMemorySize, attn_smem);

    zero_cnt<<<1, 32>>>();
    gate_kernel<<<NT, 256>>>(x, noise, Wg, Wn);
    round_permute_x<<<(NT * CC / 8) / 256, 256>>>(x);
    prep_w<<<dim3(4, 128, 18), 256>>>(Wk, Wv, Wq, Wo);

    gemm_mma<<<dim3(8, 32, 2), 128, gemm_smem>>>(pxp, pwp, pkv, 3);            // k|v
    gemm_mma<<<dim3(8, 32, 8), 128, gemm_smem>>>(pxp, pwp + 2 * MEG, pq, 1);   // q_sel

    transpose_v<<<dim3(32, 2, 64), 256>>>();

    attn_mma<<<dim3(8, 16, 8), 128, attn_smem>>>();

    gemm_mma<<<dim3(8, 32, 8), 128, gemm_smem>>>(pat, pwp + 10 * MEG, po, 2);  // o_sel

    combine<<<(NT * CC) / 256, 256>>>(out);
}

// round 9
// speedup vs baseline: 1.0612x; 1.0612x over previous
#include <cuda_runtime.h>
#include <math.h>
#include <cstdint>

#define TT 1024
#define CC 1024
#define EE 8
#define NT 4096   // B*T tokens
#define NR 8192   // 2 slots * NT rows
#define MEG 1048576

// ---------------- scratch (device globals; no allocs allowed) ----------------
__device__ float g_kv[(size_t)2 * NT * CC];       // [k(perm,rounded) | v(plain)]
__device__ float g_vT[(size_t)64 * 64 * TT];      // [b*16+h][d][t perm8], rounded
__device__ float g_q [(size_t)NR * CC];           // perm8 cols, rounded
__device__ float g_at[(size_t)NR * CC];           // perm8 cols, rounded
__device__ float g_o [(size_t)NR * CC];           // plain
__device__ float g_xp[(size_t)NT * CC];           // x, perm8 cols, rounded
__device__ float g_wp[(size_t)18 * MEG];          // prepped weights [k8][n][t][p]
__device__ float g_w [NR];
__device__ int   g_rl[EE][NT];
__device__ int   g_cnt[EE];

__global__ void zero_cnt() { if (threadIdx.x < EE) g_cnt[threadIdx.x] = 0; }

// ---------------- helpers ----------------
__device__ __forceinline__ uint32_t smem_u32(const void* p) {
    uint32_t a;
    asm("{ .reg .u64 t; cvta.to.shared.u64 t, %1; cvt.u32.u64 %0, t; }" : "=r"(a) : "l"(p));
    return a;
}
__device__ __forceinline__ uint32_t f2tf32(float x) {
    uint32_t u;
    asm("cvt.rna.tf32.f32 %0, %1;" : "=r"(u) : "f"(x));
    return u;
}
__device__ __forceinline__ float roundtf(float x) { return __uint_as_float(f2tf32(x)); }
__device__ __forceinline__ int perm8(int c) {
    return (c & ~7) | ((c & 3) << 1) | ((c >> 2) & 1);
}
__device__ __forceinline__ void mma_tf32(float* d, const uint32_t* a, const uint32_t* b) {
    asm volatile(
        "mma.sync.aligned.m16n8k8.row.col.f32.tf32.tf32.f32 "
        "{%0,%1,%2,%3},{%4,%5,%6,%7},{%8,%9},{%0,%1,%2,%3};"
        : "+f"(d[0]), "+f"(d[1]), "+f"(d[2]), "+f"(d[3])
        : "r"(a[0]), "r"(a[1]), "r"(a[2]), "r"(a[3]), "r"(b[0]), "r"(b[1]));
}
__device__ __forceinline__ void cp16(uint32_t dst, const void* src) {
    asm volatile("cp.async.ca.shared.global [%0], [%1], 16;" :: "r"(dst), "l"(src) : "memory");
}
#define CP_COMMIT() asm volatile("cp.async.commit_group;" ::: "memory")
#define CP_WAIT0()  asm volatile("cp.async.wait_group 0;" ::: "memory")
#define CP_WAIT1()  asm volatile("cp.async.wait_group 1;" ::: "memory")

// ---------------- gating (+ fused x round/permute) ----------------
__global__ __launch_bounds__(256) void gate_kernel(
    const float* __restrict__ x, const float* __restrict__ noise,
    const float* __restrict__ Wg, const float* __restrict__ Wn)
{
    int row = blockIdx.x;
    int tid = threadIdx.x;
    const float* xr = x + (size_t)row * CC;

    float accg[8], accn[8];
#pragma unroll
    for (int e = 0; e < 8; e++) { accg[e] = 0.f; accn[e] = 0.f; }
    for (int c = tid; c < CC; c += 256) {
        float xv = xr[c];
        const float* wg = Wg + c * 8;
        const float* wn = Wn + c * 8;
#pragma unroll
        for (int e = 0; e < 8; e++) { accg[e] += xv * wg[e]; accn[e] += xv * wn[e]; }
    }
    __shared__ float red[16][256];
#pragma unroll
    for (int e = 0; e < 8; e++) { red[e][tid] = accg[e]; red[8 + e][tid] = accn[e]; }
    __syncthreads();
    __shared__ float fin[16];
    if (tid < 16) {
        float s = 0.f;
        for (int i = 0; i < 256; i++) s += red[tid][i];
        fin[tid] = s;
    }
    // fused: write rounded+perm8 x row (L1-hot)
    if (tid < 128) {
        const float* src = xr + tid * 8;
        float4 a = *(const float4*)src;
        float4 b = *(const float4*)(src + 4);
        float* dst = g_xp + (size_t)row * CC + tid * 8;
        *(float4*)dst       = make_float4(roundtf(a.x), roundtf(b.x), roundtf(a.y), roundtf(b.y));
        *(float4*)(dst + 4) = make_float4(roundtf(a.z), roundtf(b.z), roundtf(a.w), roundtf(b.w));
    }
    __syncthreads();
    if (tid == 0) {
        float logit[8];
#pragma unroll
        for (int e = 0; e < 8; e++) {
            float z  = fin[8 + e];
            float sp = (z > 20.f) ? z : log1pf(expf(z));
            logit[e] = fin[e] + noise[row * 8 + e] * sp;
        }
        int i0 = 0; float v0 = logit[0];
#pragma unroll
        for (int e = 1; e < 8; e++) if (logit[e] > v0) { v0 = logit[e]; i0 = e; }
        int i1 = -1; float v1 = -INFINITY;
#pragma unroll
        for (int e = 0; e < 8; e++) if (e != i0 && logit[e] > v1) { v1 = logit[e]; i1 = e; }
        float p1 = 1.f / (1.f + expf(v0 - v1));
        float p0 = 1.f - p1;
        g_w[row]      = p0;
        g_w[NT + row] = p1;
        int pos0 = atomicAdd(&g_cnt[i0], 1); g_rl[i0][pos0] = row;
        int pos1 = atomicAdd(&g_cnt[i1], 1); g_rl[i1][pos1] = NT + row;
    }
}

// ---------------- weight prep: round + interleave [k8][n][t][p] ----------------
// z: 0=Wk, 1=Wv, 2..9=Wq[e], 10..17=Wo[e]
__global__ __launch_bounds__(256) void prep_w(
    const float* __restrict__ Wk, const float* __restrict__ Wv,
    const float* __restrict__ Wq, const float* __restrict__ Wo)
{
    int z = blockIdx.z;
    const float* src = (z == 0) ? Wk : (z == 1) ? Wv :
                       (z < 10) ? Wq + (size_t)(z - 2) * MEG : Wo + (size_t)(z - 10) * MEG;
    float* dst = g_wp + (size_t)z * MEG;
    int k8 = blockIdx.y;
    int n  = blockIdx.x * 256 + threadIdx.x;
    float v[8];
#pragma unroll
    for (int t = 0; t < 8; t++) v[t] = src[(size_t)(k8 * 8 + t) * CC + n];
    float4 o0 = make_float4(roundtf(v[0]), roundtf(v[4]), roundtf(v[1]), roundtf(v[5]));
    float4 o1 = make_float4(roundtf(v[2]), roundtf(v[6]), roundtf(v[3]), roundtf(v[7]));
    float* d = dst + ((size_t)k8 * 1024 + n) * 8;
    *(float4*)d = o0;
    *(float4*)(d + 4) = o1;
}

// ---------------- V transpose per (b,h): [t][d] -> [d][perm8(t)], rounded ----------------
__global__ __launch_bounds__(256) void transpose_v()
{
    __shared__ float tile[32][33];
    int bh = blockIdx.z;
    int b = bh >> 4, h = bh & 15;
    int t0 = blockIdx.x * 32, d0 = blockIdx.y * 32;
    int tx = threadIdx.x & 31, ty = threadIdx.x >> 5;
    const float* src = g_kv + (size_t)NT * CC;
#pragma unroll
    for (int r = 0; r < 4; r++) {
        int tt = t0 + ty + r * 8;
        tile[ty + r * 8][tx] = src[(size_t)(b * TT + tt) * CC + h * 64 + d0 + tx];
    }
    __syncthreads();
#pragma unroll
    for (int r = 0; r < 4; r++) {
        int dd = d0 + ty + r * 8;
        g_vT[((size_t)bh * 64 + dd) * TT + perm8(t0 + tx)] = roundtf(tile[tx][ty + r * 8]);
    }
}

// ---------------- tf32 mma GEMM: 256 thr, 8 warps x (64x32), cp.async 3-stage ----------------
// A (g_xp/g_at) has perm8 cols; B = g_wp slab. mode 3: dense k/v fused.
// mode 1: gather token rows. mode 2: gather direct rows.
#define AST 40
#define GS_A (128 * AST)   // floats per stage
#define GS_B (4 * 1024)
__global__ __launch_bounds__(256) void gemm_mma(
    const float* __restrict__ A, const float* __restrict__ Bp,
    float* __restrict__ C, int mode)
{
    extern __shared__ float smg[];
    float* As = smg;                 // [3][128][40]
    float* Bs = smg + 3 * GS_A;      // [3][4][1024]
    __shared__ int s_src[128];
    __shared__ int s_dst[128];

    int tid = threadIdx.x, lane = tid & 31, wid = tid >> 5;
    int z = blockIdx.z, row0 = blockIdx.y * 128, n0 = blockIdx.x * 128;

    const float* Wb;
    float* Cout = C;
    int cnt = NT;
    int prm;                          // permute+round output?
    if (mode == 3) {
        Wb = g_wp + (size_t)z * MEG;
        Cout = C + (size_t)z * NT * CC;
        prm = (z == 0);
    } else {
        Wb = Bp + (size_t)z * MEG;
        cnt = g_cnt[z];
        if (row0 >= cnt) return;
        prm = (mode == 1);
    }
    if (tid < 128) {
        int gr = row0 + tid;
        if (mode == 3) { s_src[tid] = gr; s_dst[tid] = gr; }
        else if (gr < cnt) {
            int r = g_rl[z][gr];
            s_src[tid] = (mode == 1) ? (r & (NT - 1)) : r;
            s_dst[tid] = r;
        } else { s_src[tid] = 0; s_dst[tid] = -1; }
    }
    __syncthreads();

    uint32_t sbA = smem_u32(As);
    uint32_t sbB = smem_u32(Bs);
    // A staging: 1024 cp16/chunk; thread does 4: lin = tid + j*256, r=lin>>3, g=lin&7
    const float* aptr[4];
    uint32_t adst[4];
#pragma unroll
    for (int j = 0; j < 4; j++) {
        int lin = tid + j * 256;
        int r = lin >> 3, g = lin & 7;
        aptr[j] = A + (size_t)s_src[r] * CC + g * 4;
        adst[j] = sbA + (uint32_t)(r * AST + g * 4) * 4;
    }
    const float* bbase = Wb + (size_t)n0 * 8;

    auto issue = [&](int c, int stg) {
        uint32_t ao = (uint32_t)stg * GS_A * 4;
        uint32_t bo = (uint32_t)stg * GS_B * 4;
#pragma unroll
        for (int j = 0; j < 4; j++) cp16(adst[j] + ao, aptr[j] + c * 32);
#pragma unroll
        for (int j = 0; j < 4; j++) {
            int lin = tid + j * 256;
            int k8l = lin >> 8, q = lin & 255;
            cp16(sbB + bo + (uint32_t)(k8l * 1024 + q * 4) * 4,
                 bbase + (size_t)(4 * c + k8l) * 8192 + q * 4);
        }
        CP_COMMIT();
    };

    float acc[4][4][4];
#pragma unroll
    for (int mt = 0; mt < 4; mt++)
#pragma unroll
        for (int nt = 0; nt < 4; nt++)
#pragma unroll
            for (int q = 0; q < 4; q++) acc[mt][nt][q] = 0.f;

    int wm = (wid >> 2) * 64;        // {0,64}
    int wn = (wid & 3) * 32;         // {0,32,64,96}

    issue(0, 0); issue(1, 1);
#pragma unroll 1
    for (int c = 0; c < 32; c++) {
        int stg = c % 3;
        CP_WAIT1();
        __syncthreads();
        if (c + 2 < 32) issue(c + 2, (c + 2) % 3);
        const float* Ab = As + stg * GS_A;
        const float* Bb = Bs + stg * GS_B;
#pragma unroll
        for (int k8 = 0; k8 < 4; k8++) {
            int kcol = k8 * 8 + (lane & 3) * 2;
            uint32_t af[4][4];
#pragma unroll
            for (int mt = 0; mt < 4; mt++) {
                int r = wm + mt * 16 + (lane >> 2);
                float2 lo = *(const float2*)(Ab + r * AST + kcol);
                float2 hi = *(const float2*)(Ab + (r + 8) * AST + kcol);
                af[mt][0] = __float_as_uint(lo.x); af[mt][1] = __float_as_uint(hi.x);
                af[mt][2] = __float_as_uint(lo.y); af[mt][3] = __float_as_uint(hi.y);
            }
#pragma unroll
            for (int nt = 0; nt < 4; nt++) {
                int n = wn + nt * 8 + (lane >> 2);
                float2 bv = *(const float2*)(Bb + k8 * 1024 + n * 8 + (lane & 3) * 2);
                uint32_t bf[2] = { __float_as_uint(bv.x), __float_as_uint(bv.y) };
#pragma unroll
                for (int mt = 0; mt < 4; mt++)
                    mma_tf32(acc[mt][nt], af[mt], bf);
            }
        }
    }

    int r0 = wm + (lane >> 2);
    int cb = n0 + wn + (lane & 3) * 2;
#pragma unroll
    for (int mt = 0; mt < 4; mt++) {
        int dA = s_dst[r0 + mt * 16];
        int dB = s_dst[r0 + mt * 16 + 8];
#pragma unroll
        for (int nt = 0; nt < 4; nt++) {
            int gc = cb + nt * 8;
            if (prm) {
                int p0 = perm8(gc), p1 = perm8(gc + 1);
                if (dA >= 0) {
                    Cout[(size_t)dA * CC + p0] = roundtf(acc[mt][nt][0]);
                    Cout[(size_t)dA * CC + p1] = roundtf(acc[mt][nt][1]);
                }
                if (dB >= 0) {
                    Cout[(size_t)dB * CC + p0] = roundtf(acc[mt][nt][2]);
                    Cout[(size_t)dB * CC + p1] = roundtf(acc[mt][nt][3]);
                }
            } else {
                if (dA >= 0)
                    *(float2*)(Cout + (size_t)dA * CC + gc) = make_float2(acc[mt][nt][0], acc[mt][nt][1]);
                if (dB >= 0)
                    *(float2*)(Cout + (size_t)dB * CC + gc) = make_float2(acc[mt][nt][2], acc[mt][nt][3]);
            }
        }
    }
}

// ---------------- flash attention, tf32 mma, 256 thr = 8 warps x 16 rows ----------------
// grid (8 qtiles, 16 heads, 8 = slot*4+b)
#define QST 72
__global__ __launch_bounds__(256) void attn_mma()
{
    extern __shared__ float sm[];
    float* Qs = sm;                    // [128][72] perm8 d-cols
    float* Ks = sm + 128 * QST;        // [64][72]  perm8 d-cols
    float* Vt = Ks + 64 * QST;         // [64 d][72] perm8 j-cols
    float* Ps = Vt + 64 * QST;         // [128][72] perm8 j-cols

    int tid = threadIdx.x, lane = tid & 31, wid = tid >> 5;   // wid 0..7
    int qt = 7 - (int)blockIdx.x;
    int h  = blockIdx.y;
    int zb = blockIdx.z;
    int s = zb >> 2, b = zb & 3;
    int rbase = s * NT + b * TT;
    const float* qsrc  = g_q + (size_t)(rbase + qt * 128) * CC + h * 64;
    const float* ksrc  = g_kv + (size_t)(b * TT) * CC + h * 64;
    const float* vtsrc = g_vT + (size_t)(b * 16 + h) * 64 * TT;

    uint32_t sQ = smem_u32(Qs), sK = smem_u32(Ks), sV = smem_u32(Vt);

    auto issueK = [&](int kt) {
        const float* src = ksrc + (size_t)(kt * 64) * CC;
#pragma unroll
        for (int j = 0; j < 4; j++) {
            int lin = tid + j * 256;           // 1024 cp16
            int r = lin >> 4, g = lin & 15;
            cp16(sK + (uint32_t)(r * QST + g * 4) * 4, src + (size_t)r * CC + g * 4);
        }
        CP_COMMIT();
    };
    auto issueV = [&](int kt) {
#pragma unroll
        for (int j = 0; j < 4; j++) {
            int lin = tid + j * 256;
            int d = lin >> 4, g = lin & 15;
            cp16(sV + (uint32_t)(d * QST + g * 4) * 4,
                 vtsrc + (size_t)d * TT + kt * 64 + g * 4);
        }
        CP_COMMIT();
    };

    // prologue: stage Q + K0 in one group
    {
#pragma unroll
        for (int j = 0; j < 8; j++) {
            int lin = tid + j * 256;           // 2048 cp16
            int r = lin >> 4, g = lin & 15;
            cp16(sQ + (uint32_t)(r * QST + g * 4) * 4, qsrc + (size_t)r * CC + g * 4);
        }
        issueK(0);                             // commits Q+K together
    }

    float Oa[8][4];
    float mrow[2], lrow[2];
#pragma unroll
    for (int nt = 0; nt < 8; nt++)
#pragma unroll
        for (int q = 0; q < 4; q++) Oa[nt][q] = 0.f;
    mrow[0] = mrow[1] = -1e30f;
    lrow[0] = lrow[1] = 0.f;

    int ktmax = 2 * qt + 1;
#pragma unroll 1
    for (int kt = 0; kt <= ktmax; kt++) {
        CP_WAIT0();            // K(kt) landed
        __syncthreads();       // all warps past previous PV (Vt free)
        issueV(kt);

        // S = Q @ K^T  (warp rows: wid*16 .. +15)
        float sa[8][4];
#pragma unroll
        for (int nt = 0; nt < 8; nt++)
#pragma unroll
            for (int q = 0; q < 4; q++) sa[nt][q] = 0.f;
#pragma unroll
        for (int k8 = 0; k8 < 8; k8++) {
            int kcol = k8 * 8 + (lane & 3) * 2;
            int r = wid * 16 + (lane >> 2);
            float2 lo = *(const float2*)(Qs + r * QST + kcol);
            float2 hi = *(const float2*)(Qs + (r + 8) * QST + kcol);
            uint32_t af[4] = { __float_as_uint(lo.x), __float_as_uint(hi.x),
                               __float_as_uint(lo.y), __float_as_uint(hi.y) };
#pragma unroll
            for (int nt = 0; nt < 8; nt++) {
                int n = nt * 8 + (lane >> 2);
                float2 bv = *(const float2*)(Ks + n * QST + kcol);
                uint32_t bf[2] = { __float_as_uint(bv.x), __float_as_uint(bv.y) };
                mma_tf32(sa[nt], af, bf);
            }
        }

        // online softmax + P store (perm8 cols, rounded)
        bool domask = (kt >= 2 * qt);
#pragma unroll
        for (int half = 0; half < 2; half++) {
            int rl = wid * 16 + (lane >> 2) + half * 8;
            int ig = qt * 128 + rl;
            float v[16];
#pragma unroll
            for (int nt = 0; nt < 8; nt++) {
                float s0 = sa[nt][half * 2 + 0] * 0.125f;
                float s1 = sa[nt][half * 2 + 1] * 0.125f;
                if (domask) {
                    int jg = kt * 64 + nt * 8 + 2 * (lane & 3);
                    if (jg > ig)     s0 = -1e30f;
                    if (jg + 1 > ig) s1 = -1e30f;
                }
                v[nt * 2] = s0; v[nt * 2 + 1] = s1;
            }
            float rm = v[0];
#pragma unroll
            for (int j = 1; j < 16; j++) rm = fmaxf(rm, v[j]);
            rm = fmaxf(rm, __shfl_xor_sync(0xFFFFFFFFu, rm, 1));
            rm = fmaxf(rm, __shfl_xor_sync(0xFFFFFFFFu, rm, 2));
            float mn = fmaxf(mrow[half], rm);
            float alpha = __expf(mrow[half] - mn);
            float rs = 0.f;
#pragma unroll
            for (int j = 0; j < 16; j++) { float p = __expf(v[j] - mn); v[j] = p; rs += p; }
            rs += __shfl_xor_sync(0xFFFFFFFFu, rs, 1);
            rs += __shfl_xor_sync(0xFFFFFFFFu, rs, 2);
            mrow[half] = mn;
            lrow[half] = lrow[half] * alpha + rs;
#pragma unroll
            for (int nt = 0; nt < 8; nt++) {
                Oa[nt][half * 2 + 0] *= alpha;
                Oa[nt][half * 2 + 1] *= alpha;
            }
            float* pr = Ps + rl * QST;
#pragma unroll
            for (int nt = 0; nt < 8; nt++) {
                int j0 = nt * 8 + 2 * (lane & 3);
                pr[perm8(j0)]     = roundtf(v[nt * 2]);
                pr[perm8(j0 + 1)] = roundtf(v[nt * 2 + 1]);
            }
        }
        __syncwarp();

        CP_WAIT0();            // V(kt) landed
        __syncthreads();       // all warps done reading Ks
        if (kt < ktmax) issueK(kt + 1);

        // O += P @ V  (A = own 16-row band of Ps)
#pragma unroll
        for (int k8 = 0; k8 < 8; k8++) {
            int kcol = k8 * 8 + (lane & 3) * 2;
            int r = wid * 16 + (lane >> 2);
            float2 lo = *(const float2*)(Ps + r * QST + kcol);
            float2 hi = *(const float2*)(Ps + (r + 8) * QST + kcol);
            uint32_t af[4] = { __float_as_uint(lo.x), __float_as_uint(hi.x),
                               __float_as_uint(lo.y), __float_as_uint(hi.y) };
#pragma unroll
            for (int nt = 0; nt < 8; nt++) {
                int n = nt * 8 + (lane >> 2);
                float2 bv = *(const float2*)(Vt + n * QST + kcol);
                uint32_t bf[2] = { __float_as_uint(bv.x), __float_as_uint(bv.y) };
                mma_tf32(Oa[nt], af, bf);
            }
        }
    }

    // write O: perm8 cols + rounded (pre-rounds the o-GEMM A operand)
#pragma unroll
    for (int half = 0; half < 2; half++) {
        int rl = wid * 16 + (lane >> 2) + half * 8;
        float inv = 1.f / lrow[half];
        float* orow = g_at + (size_t)(rbase + qt * 128 + rl) * CC;
#pragma unroll
        for (int nt = 0; nt < 8; nt++) {
            int c0 = h * 64 + nt * 8 + 2 * (lane & 3);
            orow[perm8(c0)]     = roundtf(Oa[nt][half * 2 + 0] * inv);
            orow[perm8(c0 + 1)] = roundtf(Oa[nt][half * 2 + 1] * inv);
        }
    }
}

// ---------------- final combine ----------------
__global__ void combine(float* __restrict__ out)
{
    int i = blockIdx.x * 256 + threadIdx.x;
    int token = i >> 10;
    out[i] = g_w[token] * g_o[i] + g_w[NT + token] * g_o[(size_t)NT * CC + i];
}

// ---------------- launch ----------------
extern "C" void kernel_launch(void* const* d_in, const int* in_sizes, int n_in,
                              void* d_out, int out_size)
{
    const float* x     = (const float*)d_in[0];
    const float* noise = (const float*)d_in[1];
    const float* Wk    = (const float*)d_in[2];
    const float* Wv    = (const float*)d_in[3];
    const float* Wq    = (const float*)d_in[4];
    const float* Wo    = (const float*)d_in[5];
    const float* Wg    = (const float*)d_in[6];
    const float* Wn    = (const float*)d_in[7];
    float* out = (float*)d_out;

    float *pkv, *pq, *pat, *po, *pxp, *pwp;
    cudaGetSymbolAddress((void**)&pkv, g_kv);
    cudaGetSymbolAddress((void**)&pq,  g_q);
    cudaGetSymbolAddress((void**)&pat, g_at);
    cudaGetSymbolAddress((void**)&po,  g_o);
    cudaGetSymbolAddress((void**)&pxp, g_xp);
    cudaGetSymbolAddress((void**)&pwp, g_wp);

    const int gemm_smem = (3 * GS_A + 3 * GS_B) * 4;       // 110592
    const int attn_smem = (128 + 64 + 64 + 128) * QST * 4; // 110592
    cudaFuncSetAttribute(gemm_mma, cudaFuncAttributeMaxDynamicSharedMemorySize, gemm_smem);
    cudaFuncSetAttribute(attn_mma, cudaFuncAttributeMaxDynamicSharedMemorySize, attn_smem);

    zero_cnt<<<1, 32>>>();
    gate_kernel<<<NT, 256>>>(x, noise, Wg, Wn);
    prep_w<<<dim3(4, 128, 18), 256>>>(Wk, Wv, Wq, Wo);

    gemm_mma<<<dim3(8, 32, 2), 256, gemm_smem>>>(pxp, pwp, pkv, 3);            // k|v
    gemm_mma<<<dim3(8, 32, 8), 256, gemm_smem>>>(pxp, pwp + 2 * MEG, pq, 1);   // q_sel

    transpose_v<<<dim3(32, 2, 64), 256>>>();

    attn_mma<<<dim3(8, 16, 8), 256, attn_smem>>>();

    gemm_mma<<<dim3(8, 32, 8), 256, gemm_smem>>>(pat, pwp + 10 * MEG, po, 2);  // o_sel

    combine<<<(NT * CC) / 256, 256>>>(out);
}

// round 10
// speedup vs baseline: 1.9342x; 1.8227x over previous
#include <cuda_runtime.h>
#include <cuda_fp16.h>
#include <math.h>
#include <cstdint>

#define TT 1024
#define CC 1024
#define EE 8
#define NT 4096   // B*T tokens
#define NR 8192   // 2 slots * NT rows
#define MEG 1048576

// ---------------- scratch (device globals; no allocs allowed) ----------------
__device__ __half g_xh [(size_t)NT * CC];        // x, fp16
__device__ __half g_kh [(size_t)NT * CC];        // k, fp16
__device__ __half g_vh [(size_t)NT * CC];        // v, fp16
__device__ __half g_vTh[(size_t)64 * 64 * TT];   // [b*16+h][d][t], fp16
__device__ __half g_qh [(size_t)NR * CC];        // q gathered, fp16
__device__ __half g_ath[(size_t)NR * CC];        // attention out, fp16
__device__ float  g_o  [(size_t)NR * CC];        // o gathered, fp32
__device__ __half g_wt [(size_t)18 * MEG];       // transposed weights [z][n][k], fp16
__device__ float  g_w  [NR];
__device__ int    g_rl[EE][NT];
__device__ int    g_cnt[EE];

__global__ void zero_cnt() { if (threadIdx.x < EE) g_cnt[threadIdx.x] = 0; }

// ---------------- helpers ----------------
__device__ __forceinline__ uint32_t smem_u32(const void* p) {
    uint32_t a;
    asm("{ .reg .u64 t; cvta.to.shared.u64 t, %1; cvt.u32.u64 %0, t; }" : "=r"(a) : "l"(p));
    return a;
}
__device__ __forceinline__ void ldsm4(uint32_t& r0, uint32_t& r1, uint32_t& r2, uint32_t& r3,
                                      uint32_t addr) {
    asm volatile("ldmatrix.sync.aligned.m8n8.x4.shared.b16 {%0,%1,%2,%3}, [%4];"
                 : "=r"(r0), "=r"(r1), "=r"(r2), "=r"(r3) : "r"(addr));
}
__device__ __forceinline__ void mma_f16(float* d, const uint32_t* a, const uint32_t* b) {
    asm volatile(
        "mma.sync.aligned.m16n8k16.row.col.f32.f16.f16.f32 "
        "{%0,%1,%2,%3},{%4,%5,%6,%7},{%8,%9},{%0,%1,%2,%3};"
        : "+f"(d[0]), "+f"(d[1]), "+f"(d[2]), "+f"(d[3])
        : "r"(a[0]), "r"(a[1]), "r"(a[2]), "r"(a[3]), "r"(b[0]), "r"(b[1]));
}
__device__ __forceinline__ void cp16(uint32_t dst, const void* src) {
    asm volatile("cp.async.ca.shared.global [%0], [%1], 16;" :: "r"(dst), "l"(src) : "memory");
}
#define CP_COMMIT() asm volatile("cp.async.commit_group;" ::: "memory")
#define CP_WAIT0()  asm volatile("cp.async.wait_group 0;" ::: "memory")
#define CP_WAIT1()  asm volatile("cp.async.wait_group 1;" ::: "memory")

// ---------------- gating (+ fused x -> fp16) ----------------
__global__ __launch_bounds__(256) void gate_kernel(
    const float* __restrict__ x, const float* __restrict__ noise,
    const float* __restrict__ Wg, const float* __restrict__ Wn)
{
    int row = blockIdx.x;
    int tid = threadIdx.x;
    const float* xr = x + (size_t)row * CC;

    float accg[8], accn[8];
#pragma unroll
    for (int e = 0; e < 8; e++) { accg[e] = 0.f; accn[e] = 0.f; }
    for (int c = tid; c < CC; c += 256) {
        float xv = xr[c];
        const float* wg = Wg + c * 8;
        const float* wn = Wn + c * 8;
#pragma unroll
        for (int e = 0; e < 8; e++) { accg[e] += xv * wg[e]; accn[e] += xv * wn[e]; }
    }
    __shared__ float red[16][256];
#pragma unroll
    for (int e = 0; e < 8; e++) { red[e][tid] = accg[e]; red[8 + e][tid] = accn[e]; }
    __syncthreads();
    __shared__ float fin[16];
    if (tid < 16) {
        float s = 0.f;
        for (int i = 0; i < 256; i++) s += red[tid][i];
        fin[tid] = s;
    }
    // fused: x row -> fp16 (L1-hot)
    {
        int c = tid * 4;
        float4 vv = *(const float4*)(xr + c);
        __half2* dst = (__half2*)(g_xh + (size_t)row * CC + c);
        dst[0] = __floats2half2_rn(vv.x, vv.y);
        dst[1] = __floats2half2_rn(vv.z, vv.w);
    }
    __syncthreads();
    if (tid == 0) {
        float logit[8];
#pragma unroll
        for (int e = 0; e < 8; e++) {
            float z  = fin[8 + e];
            float sp = (z > 20.f) ? z : log1pf(expf(z));
            logit[e] = fin[e] + noise[row * 8 + e] * sp;
        }
        int i0 = 0; float v0 = logit[0];
#pragma unroll
        for (int e = 1; e < 8; e++) if (logit[e] > v0) { v0 = logit[e]; i0 = e; }
        int i1 = -1; float v1 = -INFINITY;
#pragma unroll
        for (int e = 0; e < 8; e++) if (e != i0 && logit[e] > v1) { v1 = logit[e]; i1 = e; }
        float p1 = 1.f / (1.f + expf(v0 - v1));
        float p0 = 1.f - p1;
        g_w[row]      = p0;
        g_w[NT + row] = p1;
        int pos0 = atomicAdd(&g_cnt[i0], 1); g_rl[i0][pos0] = row;
        int pos1 = atomicAdd(&g_cnt[i1], 1); g_rl[i1][pos1] = NT + row;
    }
}

// ---------------- weight prep: transpose [k][n] -> [n][k], fp16 ----------------
// z: 0=Wk, 1=Wv, 2..9=Wq[e], 10..17=Wo[e]
__global__ __launch_bounds__(256) void prep_w(
    const float* __restrict__ Wk, const float* __restrict__ Wv,
    const float* __restrict__ Wq, const float* __restrict__ Wo)
{
    __shared__ float tile[32][33];
    int z = blockIdx.z;
    const float* src = (z == 0) ? Wk : (z == 1) ? Wv :
                       (z < 10) ? Wq + (size_t)(z - 2) * MEG : Wo + (size_t)(z - 10) * MEG;
    __half* dst = g_wt + (size_t)z * MEG;
    int k0 = blockIdx.y * 32, n0 = blockIdx.x * 32;
    int tx = threadIdx.x & 31, ty = threadIdx.x >> 5;
#pragma unroll
    for (int r = 0; r < 4; r++)
        tile[ty + r * 8][tx] = src[(size_t)(k0 + ty + r * 8) * CC + n0 + tx];
    __syncthreads();
#pragma unroll
    for (int r = 0; r < 4; r++)
        dst[(size_t)(n0 + ty + r * 8) * CC + k0 + tx] = __float2half_rn(tile[tx][ty + r * 8]);
}

// ---------------- V transpose per (b,h): [t][d] -> [d][t], fp16 ----------------
__global__ __launch_bounds__(256) void transpose_v()
{
    __shared__ float tile[32][33];
    int bh = blockIdx.z;
    int b = bh >> 4, h = bh & 15;
    int t0 = blockIdx.x * 32, d0 = blockIdx.y * 32;
    int tx = threadIdx.x & 31, ty = threadIdx.x >> 5;
#pragma unroll
    for (int r = 0; r < 4; r++)
        tile[ty + r * 8][tx] =
            __half2float(g_vh[(size_t)(b * TT + t0 + ty + r * 8) * CC + h * 64 + d0 + tx]);
    __syncthreads();
#pragma unroll
    for (int r = 0; r < 4; r++)
        g_vTh[((size_t)bh * 64 + d0 + ty + r * 8) * TT + t0 + tx] =
            __float2half_rn(tile[tx][ty + r * 8]);
}

// ---------------- fp16 mma GEMM: 256 thr, 8 warps x (64x32), K chunk 64, 3-stage ----------------
// mode 0: z 0..9 (z<2: dense k/v; z>=2: gather-q for expert z-2)
// mode 2: z 0..7 (gather-o for expert z), fp32 output
#define HST 72            // halfs per stage row
#define HGS (128 * HST)   // halfs per stage (A or B)
__global__ __launch_bounds__(256) void gemm_h(int mode)
{
    extern __shared__ __half smh[];
    __half* As = smh;                 // [3][128][72]
    __half* Bs = smh + 3 * HGS;       // [3][128][72]
    __shared__ int s_src[128];
    __shared__ int s_dst[128];

    int tid = threadIdx.x, lane = tid & 31, wid = tid >> 5;
    int z = blockIdx.z, row0 = blockIdx.y * 128, n0 = blockIdx.x * 128;

    const __half* Ag;
    const __half* Bw;
    __half* Ch = nullptr;
    float*  Cf = nullptr;
    int cnt = NT, e = 0;
    bool gather;
    if (mode == 0) {
        Ag = g_xh;
        Bw = g_wt + (size_t)z * MEG;
        if (z < 2) { Ch = z ? g_vh : g_kh; gather = false; }
        else {
            e = z - 2; Ch = g_qh; gather = true;
            cnt = g_cnt[e];
            if (row0 >= cnt) return;
        }
    } else {
        e = z; Ag = g_ath;
        Bw = g_wt + (size_t)(10 + z) * MEG;
        Cf = g_o; gather = true;
        cnt = g_cnt[e];
        if (row0 >= cnt) return;
    }
    if (tid < 128) {
        int gr = row0 + tid;
        if (!gather) { s_src[tid] = gr; s_dst[tid] = gr; }
        else if (gr < cnt) {
            int r = g_rl[e][gr];
            s_src[tid] = (mode == 0) ? (r & (NT - 1)) : r;
            s_dst[tid] = r;
        } else { s_src[tid] = 0; s_dst[tid] = -1; }
    }
    __syncthreads();

    uint32_t sA = smem_u32(As), sB = smem_u32(Bs);
    const __half* aptr[4];
    const __half* bptr[4];
    uint32_t adst[4], bdst[4];
#pragma unroll
    for (int j = 0; j < 4; j++) {
        int lin = tid + j * 256;          // 0..1023
        int r = lin >> 3, g = lin & 7;    // 8 halfs = 16 B per cp
        aptr[j] = Ag + (size_t)s_src[r] * CC + g * 8;
        adst[j] = sA + (uint32_t)(r * HST + g * 8) * 2;
        bptr[j] = Bw + (size_t)(n0 + r) * CC + g * 8;
        bdst[j] = sB + (uint32_t)(r * HST + g * 8) * 2;
    }
    auto issue = [&](int c, int stg) {
        uint32_t off = (uint32_t)stg * HGS * 2;
#pragma unroll
        for (int j = 0; j < 4; j++) cp16(adst[j] + off, aptr[j] + c * 64);
#pragma unroll
        for (int j = 0; j < 4; j++) cp16(bdst[j] + off, bptr[j] + c * 64);
        CP_COMMIT();
    };

    float acc[4][4][4];
#pragma unroll
    for (int mt = 0; mt < 4; mt++)
#pragma unroll
        for (int nt = 0; nt < 4; nt++)
#pragma unroll
            for (int q = 0; q < 4; q++) acc[mt][nt][q] = 0.f;

    int wm = (wid >> 2) * 64;
    int wn = (wid & 3) * 32;
    // ldmatrix lane-address components
    int a_row = (lane & 7) + ((lane >> 3) & 1) * 8;   // + warp-tile row
    int a_col = (lane >> 4) * 8;                      // + kstep base
    int b_row = (lane & 7) + (lane >> 4) * 8;
    int b_col = ((lane >> 3) & 1) * 8;

    issue(0, 0); issue(1, 1);
#pragma unroll 1
    for (int c = 0; c < 16; c++) {
        int stg = c % 3;
        CP_WAIT1();
        __syncthreads();
        if (c + 2 < 16) issue(c + 2, (c + 2) % 3);
        uint32_t abase = sA + (uint32_t)stg * HGS * 2;
        uint32_t bbase = sB + (uint32_t)stg * HGS * 2;
#pragma unroll
        for (int ks = 0; ks < 4; ks++) {
            int kc = ks * 16;
            uint32_t af[4][4], bf[4][2];
#pragma unroll
            for (int mt = 0; mt < 4; mt++) {
                int r = wm + mt * 16 + a_row;
                ldsm4(af[mt][0], af[mt][1], af[mt][2], af[mt][3],
                      abase + (uint32_t)(r * HST + kc + a_col) * 2);
            }
#pragma unroll
            for (int p = 0; p < 2; p++) {
                int nr = wn + p * 16 + b_row;
                uint32_t r0, r1, r2, r3;
                ldsm4(r0, r1, r2, r3, bbase + (uint32_t)(nr * HST + kc + b_col) * 2);
                bf[2 * p][0] = r0; bf[2 * p][1] = r1;
                bf[2 * p + 1][0] = r2; bf[2 * p + 1][1] = r3;
            }
#pragma unroll
            for (int mt = 0; mt < 4; mt++)
#pragma unroll
                for (int nt = 0; nt < 4; nt++)
                    mma_f16(acc[mt][nt], af[mt], bf[nt]);
        }
    }

    int r0l = wm + (lane >> 2);
    int cb = n0 + wn + (lane & 3) * 2;
#pragma unroll
    for (int mt = 0; mt < 4; mt++) {
        int dA = s_dst[r0l + mt * 16];
        int dB = s_dst[r0l + mt * 16 + 8];
#pragma unroll
        for (int nt = 0; nt < 4; nt++) {
            int gc = cb + nt * 8;
            if (mode == 0) {
                if (dA >= 0)
                    *(__half2*)(Ch + (size_t)dA * CC + gc) =
                        __floats2half2_rn(acc[mt][nt][0], acc[mt][nt][1]);
                if (dB >= 0)
                    *(__half2*)(Ch + (size_t)dB * CC + gc) =
                        __floats2half2_rn(acc[mt][nt][2], acc[mt][nt][3]);
            } else {
                if (dA >= 0)
                    *(float2*)(Cf + (size_t)dA * CC + gc) = make_float2(acc[mt][nt][0], acc[mt][nt][1]);
                if (dB >= 0)
                    *(float2*)(Cf + (size_t)dB * CC + gc) = make_float2(acc[mt][nt][2], acc[mt][nt][3]);
            }
        }
    }
}

// ---------------- flash attention, fp16 mma: 256 thr = 8 warps x 16 rows ----------------
// grid (8 qtiles, 16 heads, 8 = slot*4+b)
__global__ __launch_bounds__(256) void attn_h()
{
    extern __shared__ __half smh[];
    __half* Qs = smh;                  // [128][72]
    __half* Ks = smh + 128 * HST;      // [64][72]
    __half* Vt = Ks + 64 * HST;        // [64 d][72 j]
    __half* Ps = Vt + 64 * HST;        // [128][72]

    int tid = threadIdx.x, lane = tid & 31, wid = tid >> 5;
    int qt = 7 - (int)blockIdx.x;      // longest first
    int h  = blockIdx.y;
    int zb = blockIdx.z;
    int s = zb >> 2, b = zb & 3;
    int rbase = s * NT + b * TT;
    const __half* qsrc  = g_qh + (size_t)(rbase + qt * 128) * CC + h * 64;
    const __half* ksrc  = g_kh + (size_t)(b * TT) * CC + h * 64;
    const __half* vtsrc = g_vTh + (size_t)(b * 16 + h) * 64 * TT;

    uint32_t sQ = smem_u32(Qs), sK = smem_u32(Ks), sV = smem_u32(Vt), sP = smem_u32(Ps);

    auto issueK = [&](int kt) {
        const __half* src = ksrc + (size_t)(kt * 64) * CC;
#pragma unroll
        for (int j = 0; j < 2; j++) {
            int lin = tid + j * 256;          // 512 cp16
            int r = lin >> 3, g = lin & 7;
            cp16(sK + (uint32_t)(r * HST + g * 8) * 2, src + (size_t)r * CC + g * 8);
        }
        CP_COMMIT();
    };
    auto issueV = [&](int kt) {
#pragma unroll
        for (int j = 0; j < 2; j++) {
            int lin = tid + j * 256;
            int d = lin >> 3, g = lin & 7;
            cp16(sV + (uint32_t)(d * HST + g * 8) * 2,
                 vtsrc + (size_t)d * TT + kt * 64 + g * 8);
        }
        CP_COMMIT();
    };

    // prologue: stage Q + K0 in one group
    {
#pragma unroll
        for (int j = 0; j < 4; j++) {
            int lin = tid + j * 256;          // 1024 cp16
            int r = lin >> 3, g = lin & 7;
            cp16(sQ + (uint32_t)(r * HST + g * 8) * 2, qsrc + (size_t)r * CC + g * 8);
        }
        issueK(0);
    }

    float Oa[8][4];
    float mrow[2], lrow[2];
#pragma unroll
    for (int nt = 0; nt < 8; nt++)
#pragma unroll
        for (int q = 0; q < 4; q++) Oa[nt][q] = 0.f;
    mrow[0] = mrow[1] = -1e30f;
    lrow[0] = lrow[1] = 0.f;

    int a_row = (lane & 7) + ((lane >> 3) & 1) * 8;
    int a_col = (lane >> 4) * 8;
    int b_row = (lane & 7) + (lane >> 4) * 8;
    int b_col = ((lane >> 3) & 1) * 8;

    int ktmax = 2 * qt + 1;
#pragma unroll 1
    for (int kt = 0; kt <= ktmax; kt++) {
        CP_WAIT0();            // K(kt) landed
        __syncthreads();       // all warps past previous PV (Vt free)
        issueV(kt);

        // S = Q @ K^T  (warp rows: wid*16..+15)
        float sa[8][4];
#pragma unroll
        for (int nt = 0; nt < 8; nt++)
#pragma unroll
            for (int q = 0; q < 4; q++) sa[nt][q] = 0.f;
#pragma unroll
        for (int ks = 0; ks < 4; ks++) {
            int kc = ks * 16;
            uint32_t af[4];
            {
                int r = wid * 16 + a_row;
                ldsm4(af[0], af[1], af[2], af[3], sQ + (uint32_t)(r * HST + kc + a_col) * 2);
            }
#pragma unroll
            for (int p = 0; p < 4; p++) {
                int nr = p * 16 + b_row;
                uint32_t r0, r1, r2, r3;
                ldsm4(r0, r1, r2, r3, sK + (uint32_t)(nr * HST + kc + b_col) * 2);
                uint32_t bf0[2] = { r0, r1 }, bf1[2] = { r2, r3 };
                mma_f16(sa[2 * p],     af, bf0);
                mma_f16(sa[2 * p + 1], af, bf1);
            }
        }

        // online softmax + P store (fp16)
        bool domask = (kt >= 2 * qt);
#pragma unroll
        for (int half = 0; half < 2; half++) {
            int rl = wid * 16 + (lane >> 2) + half * 8;
            int ig = qt * 128 + rl;
            float v[16];
#pragma unroll
            for (int nt = 0; nt < 8; nt++) {
                float s0 = sa[nt][half * 2 + 0] * 0.125f;
                float s1 = sa[nt][half * 2 + 1] * 0.125f;
                if (domask) {
                    int jg = kt * 64 + nt * 8 + 2 * (lane & 3);
                    if (jg > ig)     s0 = -1e30f;
                    if (jg + 1 > ig) s1 = -1e30f;
                }
                v[nt * 2] = s0; v[nt * 2 + 1] = s1;
            }
            float rm = v[0];
#pragma unroll
            for (int j = 1; j < 16; j++) rm = fmaxf(rm, v[j]);
            rm = fmaxf(rm, __shfl_xor_sync(0xFFFFFFFFu, rm, 1));
            rm = fmaxf(rm, __shfl_xor_sync(0xFFFFFFFFu, rm, 2));
            float mn = fmaxf(mrow[half], rm);
            float alpha = __expf(mrow[half] - mn);
            float rs = 0.f;
#pragma unroll
            for (int j = 0; j < 16; j++) { float p = __expf(v[j] - mn); v[j] = p; rs += p; }
            rs += __shfl_xor_sync(0xFFFFFFFFu, rs, 1);
            rs += __shfl_xor_sync(0xFFFFFFFFu, rs, 2);
            mrow[half] = mn;
            lrow[half] = lrow[half] * alpha + rs;
#pragma unroll
            for (int nt = 0; nt < 8; nt++) {
                Oa[nt][half * 2 + 0] *= alpha;
                Oa[nt][half * 2 + 1] *= alpha;
            }
            __half* pr = Ps + rl * HST;
#pragma unroll
            for (int nt = 0; nt < 8; nt++) {
                int j0 = nt * 8 + 2 * (lane & 3);
                *(__half2*)(pr + j0) = __floats2half2_rn(v[nt * 2], v[nt * 2 + 1]);
            }
        }
        __syncwarp();

        CP_WAIT0();            // V(kt) landed
        __syncthreads();       // all warps done reading Ks
        if (kt < ktmax) issueK(kt + 1);

        // O += P @ V  (A = own 16-row band of Ps)
#pragma unroll
        for (int ks = 0; ks < 4; ks++) {
            int kc = ks * 16;
            uint32_t af[4];
            {
                int r = wid * 16 + a_row;
                ldsm4(af[0], af[1], af[2], af[3], sP + (uint32_t)(r * HST + kc + a_col) * 2);
            }
#pragma unroll
            for (int p = 0; p < 4; p++) {
                int nr = p * 16 + b_row;
                uint32_t r0, r1, r2, r3;
                ldsm4(r0, r1, r2, r3, sV + (uint32_t)(nr * HST + kc + b_col) * 2);
                uint32_t bf0[2] = { r0, r1 }, bf1[2] = { r2, r3 };
                mma_f16(Oa[2 * p],     af, bf0);
                mma_f16(Oa[2 * p + 1], af, bf1);
            }
        }
    }

    // write O (fp16: pre-converts the o-GEMM A operand)
#pragma unroll
    for (int half = 0; half < 2; half++) {
        int rl = wid * 16 + (lane >> 2) + half * 8;
        float inv = 1.f / lrow[half];
        __half* orow = g_ath + (size_t)(rbase + qt * 128 + rl) * CC;
#pragma unroll
        for (int nt = 0; nt < 8; nt++) {
            int c0 = h * 64 + nt * 8 + 2 * (lane & 3);
            *(__half2*)(orow + c0) =
                __floats2half2_rn(Oa[nt][half * 2 + 0] * inv, Oa[nt][half * 2 + 1] * inv);
        }
    }
}

// ---------------- final combine ----------------
__global__ void combine(float* __restrict__ out)
{
    int i = blockIdx.x * 256 + threadIdx.x;
    int token = i >> 10;
    out[i] = g_w[token] * g_o[i] + g_w[NT + token] * g_o[(size_t)NT * CC + i];
}

// ---------------- launch ----------------
extern "C" void kernel_launch(void* const* d_in, const int* in_sizes, int n_in,
                              void* d_out, int out_size)
{
    const float* x     = (const float*)d_in[0];
    const float* noise = (const float*)d_in[1];
    const float* Wk    = (const float*)d_in[2];
    const float* Wv    = (const float*)d_in[3];
    const float* Wq    = (const float*)d_in[4];
    const float* Wo    = (const float*)d_in[5];
    const float* Wg    = (const float*)d_in[6];
    const float* Wn    = (const float*)d_in[7];
    float* out = (float*)d_out;

    const int gemm_smem = 6 * HGS * 2;                 // 110592
    const int attn_smem = (128 + 64 + 64 + 128) * HST * 2;  // 55296
    cudaFuncSetAttribute(gemm_h, cudaFuncAttributeMaxDynamicSharedMemorySize, gemm_smem);
    cudaFuncSetAttribute(attn_h, cudaFuncAttributeMaxDynamicSharedMemorySize, attn_smem);

    zero_cnt<<<1, 32>>>();
    gate_kernel<<<NT, 256>>>(x, noise, Wg, Wn);
    prep_w<<<dim3(32, 32, 18), 256>>>(Wk, Wv, Wq, Wo);

    gemm_h<<<dim3(8, 32, 10), 256, gemm_smem>>>(0);    // k | v | q_sel (fused)

    transpose_v<<<dim3(32, 2, 64), 256>>>();

    attn_h<<<dim3(8, 16, 8), 256, attn_smem>>>();

    gemm_h<<<dim3(8, 32, 8), 256, gemm_smem>>>(2);     // o_sel

    combine<<<(NT * CC) / 256, 256>>>(out);
}

// round 12
// speedup vs baseline: 1.9542x; 1.0104x over previous
#include <cuda_runtime.h>
#include <cuda_fp16.h>
#include <math.h>
#include <cstdint>

#define TT 1024
#define CC 1024
#define EE 8
#define NT 4096   // B*T tokens
#define NR 8192   // 2 slots * NT rows
#define MEG 1048576

// ---------------- scratch (device globals; no allocs allowed) ----------------
__device__ __half g_xh [(size_t)NT * CC];        // x, fp16
__device__ __half g_kh [(size_t)NT * CC];        // k, fp16
__device__ __half g_vh [(size_t)NT * CC];        // v, fp16
__device__ __half g_vTh[(size_t)64 * 64 * TT];   // [b*16+h][d][t], fp16
__device__ __half g_qh [(size_t)NR * CC];        // q gathered, fp16
__device__ __half g_ath[(size_t)NR * CC];        // attention out, fp16
__device__ float  g_o  [(size_t)NR * CC];        // o gathered, fp32
__device__ __half g_wt [(size_t)18 * MEG];       // transposed weights [z][n][k], fp16
__device__ float  g_w  [NR];
__device__ int    g_rl[EE][NT];
__device__ int    g_cnt[EE];

__global__ void zero_cnt() { if (threadIdx.x < EE) g_cnt[threadIdx.x] = 0; }

// ---------------- helpers ----------------
__device__ __forceinline__ uint32_t smem_u32(const void* p) {
    uint32_t a;
    asm("{ .reg .u64 t; cvta.to.shared.u64 t, %1; cvt.u32.u64 %0, t; }" : "=r"(a) : "l"(p));
    return a;
}
__device__ __forceinline__ void ldsm4(uint32_t& r0, uint32_t& r1, uint32_t& r2, uint32_t& r3,
                                      uint32_t addr) {
    asm volatile("ldmatrix.sync.aligned.m8n8.x4.shared.b16 {%0,%1,%2,%3}, [%4];"
                 : "=r"(r0), "=r"(r1), "=r"(r2), "=r"(r3) : "r"(addr));
}
__device__ __forceinline__ void mma_f16(float* d, const uint32_t* a, const uint32_t* b) {
    asm volatile(
        "mma.sync.aligned.m16n8k16.row.col.f32.f16.f16.f32 "
        "{%0,%1,%2,%3},{%4,%5,%6,%7},{%8,%9},{%0,%1,%2,%3};"
        : "+f"(d[0]), "+f"(d[1]), "+f"(d[2]), "+f"(d[3])
        : "r"(a[0]), "r"(a[1]), "r"(a[2]), "r"(a[3]), "r"(b[0]), "r"(b[1]));
}
__device__ __forceinline__ void cp16(uint32_t dst, const void* src) {
    asm volatile("cp.async.ca.shared.global [%0], [%1], 16;" :: "r"(dst), "l"(src) : "memory");
}
#define CP_COMMIT() asm volatile("cp.async.commit_group;" ::: "memory")
#define CP_WAIT0()  asm volatile("cp.async.wait_group 0;" ::: "memory")
#define CP_WAIT1()  asm volatile("cp.async.wait_group 1;" ::: "memory")

// ---------------- gating (+ fused x -> fp16) ----------------
__global__ __launch_bounds__(256) void gate_kernel(
    const float* __restrict__ x, const float* __restrict__ noise,
    const float* __restrict__ Wg, const float* __restrict__ Wn)
{
    int row = blockIdx.x;
    int tid = threadIdx.x;
    const float* xr = x + (size_t)row * CC;

    float accg[8], accn[8];
#pragma unroll
    for (int e = 0; e < 8; e++) { accg[e] = 0.f; accn[e] = 0.f; }
    for (int c = tid; c < CC; c += 256) {
        float xv = xr[c];
        const float* wg = Wg + c * 8;
        const float* wn = Wn + c * 8;
#pragma unroll
        for (int e = 0; e < 8; e++) { accg[e] += xv * wg[e]; accn[e] += xv * wn[e]; }
    }
    __shared__ float red[16][256];
#pragma unroll
    for (int e = 0; e < 8; e++) { red[e][tid] = accg[e]; red[8 + e][tid] = accn[e]; }
    __syncthreads();
    __shared__ float fin[16];
    if (tid < 16) {
        float s = 0.f;
        for (int i = 0; i < 256; i++) s += red[tid][i];
        fin[tid] = s;
    }
    // fused: x row -> fp16 (L1-hot)
    {
        int c = tid * 4;
        float4 vv = *(const float4*)(xr + c);
        __half2* dst = (__half2*)(g_xh + (size_t)row * CC + c);
        dst[0] = __floats2half2_rn(vv.x, vv.y);
        dst[1] = __floats2half2_rn(vv.z, vv.w);
    }
    __syncthreads();
    if (tid == 0) {
        float logit[8];
#pragma unroll
        for (int e = 0; e < 8; e++) {
            float z  = fin[8 + e];
            float sp = (z > 20.f) ? z : log1pf(expf(z));
            logit[e] = fin[e] + noise[row * 8 + e] * sp;
        }
        int i0 = 0; float v0 = logit[0];
#pragma unroll
        for (int e = 1; e < 8; e++) if (logit[e] > v0) { v0 = logit[e]; i0 = e; }
        int i1 = -1; float v1 = -INFINITY;
#pragma unroll
        for (int e = 0; e < 8; e++) if (e != i0 && logit[e] > v1) { v1 = logit[e]; i1 = e; }
        float p1 = 1.f / (1.f + expf(v0 - v1));
        float p0 = 1.f - p1;
        g_w[row]      = p0;
        g_w[NT + row] = p1;
        int pos0 = atomicAdd(&g_cnt[i0], 1); g_rl[i0][pos0] = row;
        int pos1 = atomicAdd(&g_cnt[i1], 1); g_rl[i1][pos1] = NT + row;
    }
}

// ---------------- weight prep: transpose [k][n] -> [n][k], fp16 ----------------
// z: 0=Wk, 1=Wv, 2..9=Wq[e], 10..17=Wo[e]
__global__ __launch_bounds__(256) void prep_w(
    const float* __restrict__ Wk, const float* __restrict__ Wv,
    const float* __restrict__ Wq, const float* __restrict__ Wo)
{
    __shared__ float tile[32][33];
    int z = blockIdx.z;
    const float* src = (z == 0) ? Wk : (z == 1) ? Wv :
                       (z < 10) ? Wq + (size_t)(z - 2) * MEG : Wo + (size_t)(z - 10) * MEG;
    __half* dst = g_wt + (size_t)z * MEG;
    int k0 = blockIdx.y * 32, n0 = blockIdx.x * 32;
    int tx = threadIdx.x & 31, ty = threadIdx.x >> 5;
#pragma unroll
    for (int r = 0; r < 4; r++)
        tile[ty + r * 8][tx] = src[(size_t)(k0 + ty + r * 8) * CC + n0 + tx];
    __syncthreads();
#pragma unroll
    for (int r = 0; r < 4; r++)
        dst[(size_t)(n0 + ty + r * 8) * CC + k0 + tx] = __float2half_rn(tile[tx][ty + r * 8]);
}

// ---------------- V transpose per (b,h): [t][d] -> [d][t], fp16 ----------------
__global__ __launch_bounds__(256) void transpose_v()
{
    __shared__ float tile[32][33];
    int bh = blockIdx.z;
    int b = bh >> 4, h = bh & 15;
    int t0 = blockIdx.x * 32, d0 = blockIdx.y * 32;
    int tx = threadIdx.x & 31, ty = threadIdx.x >> 5;
#pragma unroll
    for (int r = 0; r < 4; r++)
        tile[ty + r * 8][tx] =
            __half2float(g_vh[(size_t)(b * TT + t0 + ty + r * 8) * CC + h * 64 + d0 + tx]);
    __syncthreads();
#pragma unroll
    for (int r = 0; r < 4; r++)
        g_vTh[((size_t)bh * 64 + d0 + ty + r * 8) * TT + t0 + tx] =
            __float2half_rn(tile[tx][ty + r * 8]);
}

// ---------------- fp16 mma GEMM: 256 thr, 8 warps x (64x32), K chunk 64, 3-stage ----------------
// mode 0: z 0..9 (z<2: dense k/v; z>=2: gather-q for expert z-2)
// mode 2: z 0..7 (gather-o for expert z), fp32 output
#define HST 72            // halfs per stage row
#define HGS (128 * HST)   // halfs per stage (A or B)
__global__ __launch_bounds__(256) void gemm_h(int mode)
{
    extern __shared__ __half smh[];
    __half* As = smh;                 // [3][128][72]
    __half* Bs = smh + 3 * HGS;       // [3][128][72]
    __shared__ int s_src[128];
    __shared__ int s_dst[128];

    int tid = threadIdx.x, lane = tid & 31, wid = tid >> 5;
    int z = blockIdx.z, row0 = blockIdx.y * 128, n0 = blockIdx.x * 128;

    const __half* Ag;
    const __half* Bw;
    __half* Ch = nullptr;
    float*  Cf = nullptr;
    int cnt = NT, e = 0;
    bool gather;
    if (mode == 0) {
        Ag = g_xh;
        Bw = g_wt + (size_t)z * MEG;
        if (z < 2) { Ch = z ? g_vh : g_kh; gather = false; }
        else {
            e = z - 2; Ch = g_qh; gather = true;
            cnt = g_cnt[e];
            if (row0 >= cnt) return;
        }
    } else {
        e = z; Ag = g_ath;
        Bw = g_wt + (size_t)(10 + z) * MEG;
        Cf = g_o; gather = true;
        cnt = g_cnt[e];
        if (row0 >= cnt) return;
    }
    if (tid < 128) {
        int gr = row0 + tid;
        if (!gather) { s_src[tid] = gr; s_dst[tid] = gr; }
        else if (gr < cnt) {
            int r = g_rl[e][gr];
            s_src[tid] = (mode == 0) ? (r & (NT - 1)) : r;
            s_dst[tid] = r;
        } else { s_src[tid] = 0; s_dst[tid] = -1; }
    }
    __syncthreads();

    uint32_t sA = smem_u32(As), sB = smem_u32(Bs);
    const __half* aptr[4];
    const __half* bptr[4];
    uint32_t adst[4], bdst[4];
#pragma unroll
    for (int j = 0; j < 4; j++) {
        int lin = tid + j * 256;          // 0..1023
        int r = lin >> 3, g = lin & 7;    // 8 halfs = 16 B per cp
        aptr[j] = Ag + (size_t)s_src[r] * CC + g * 8;
        adst[j] = sA + (uint32_t)(r * HST + g * 8) * 2;
        bptr[j] = Bw + (size_t)(n0 + r) * CC + g * 8;
        bdst[j] = sB + (uint32_t)(r * HST + g * 8) * 2;
    }
    auto issue = [&](int c, int stg) {
        uint32_t off = (uint32_t)stg * HGS * 2;
#pragma unroll
        for (int j = 0; j < 4; j++) cp16(adst[j] + off, aptr[j] + c * 64);
#pragma unroll
        for (int j = 0; j < 4; j++) cp16(bdst[j] + off, bptr[j] + c * 64);
        CP_COMMIT();
    };

    float acc[4][4][4];
#pragma unroll
    for (int mt = 0; mt < 4; mt++)
#pragma unroll
        for (int nt = 0; nt < 4; nt++)
#pragma unroll
            for (int q = 0; q < 4; q++) acc[mt][nt][q] = 0.f;

    int wm = (wid >> 2) * 64;
    int wn = (wid & 3) * 32;
    // ldmatrix lane-address components
    int a_row = (lane & 7) + ((lane >> 3) & 1) * 8;   // + warp-tile row
    int a_col = (lane >> 4) * 8;                      // + kstep base
    int b_row = (lane & 7) + (lane >> 4) * 8;
    int b_col = ((lane >> 3) & 1) * 8;

    issue(0, 0); issue(1, 1);
#pragma unroll 1
    for (int c = 0; c < 16; c++) {
        int stg = c % 3;
        CP_WAIT1();
        __syncthreads();
        if (c + 2 < 16) issue(c + 2, (c + 2) % 3);
        uint32_t abase = sA + (uint32_t)stg * HGS * 2;
        uint32_t bbase = sB + (uint32_t)stg * HGS * 2;
#pragma unroll
        for (int ks = 0; ks < 4; ks++) {
            int kc = ks * 16;
            uint32_t af[4][4], bf[4][2];
#pragma unroll
            for (int mt = 0; mt < 4; mt++) {
                int r = wm + mt * 16 + a_row;
                ldsm4(af[mt][0], af[mt][1], af[mt][2], af[mt][3],
                      abase + (uint32_t)(r * HST + kc + a_col) * 2);
            }
#pragma unroll
            for (int p = 0; p < 2; p++) {
                int nr = wn + p * 16 + b_row;
                uint32_t r0, r1, r2, r3;
                ldsm4(r0, r1, r2, r3, bbase + (uint32_t)(nr * HST + kc + b_col) * 2);
                bf[2 * p][0] = r0; bf[2 * p][1] = r1;
                bf[2 * p + 1][0] = r2; bf[2 * p + 1][1] = r3;
            }
#pragma unroll
            for (int mt = 0; mt < 4; mt++)
#pragma unroll
                for (int nt = 0; nt < 4; nt++)
                    mma_f16(acc[mt][nt], af[mt], bf[nt]);
        }
    }

    int r0l = wm + (lane >> 2);
    int cb = n0 + wn + (lane & 3) * 2;
#pragma unroll
    for (int mt = 0; mt < 4; mt++) {
        int dA = s_dst[r0l + mt * 16];
        int dB = s_dst[r0l + mt * 16 + 8];
#pragma unroll
        for (int nt = 0; nt < 4; nt++) {
            int gc = cb + nt * 8;
            if (mode == 0) {
                if (dA >= 0)
                    *(__half2*)(Ch + (size_t)dA * CC + gc) =
                        __floats2half2_rn(acc[mt][nt][0], acc[mt][nt][1]);
                if (dB >= 0)
                    *(__half2*)(Ch + (size_t)dB * CC + gc) =
                        __floats2half2_rn(acc[mt][nt][2], acc[mt][nt][3]);
            } else {
                if (dA >= 0)
                    *(float2*)(Cf + (size_t)dA * CC + gc) = make_float2(acc[mt][nt][0], acc[mt][nt][1]);
                if (dB >= 0)
                    *(float2*)(Cf + (size_t)dB * CC + gc) = make_float2(acc[mt][nt][2], acc[mt][nt][3]);
            }
        }
    }
}

// ---------------- flash attention, fp16 mma: 3-buffer K+V, single barrier/tile ----------------
// grid (8 qtiles, 16 heads, 8 = slot*4+b), 256 thr = 8 warps x 16 rows
#define ATL (64 * HST)    // halfs per K or V buffer
__global__ __launch_bounds__(256) void attn_h()
{
    extern __shared__ __half smh[];
    __half* Qs = smh;                  // [128][72]
    __half* Kb = smh + 128 * HST;      // [3][64][72]
    __half* Vb = Kb + 3 * ATL;         // [3][64 d][72 j]
    __half* Ps = Vb + 3 * ATL;         // [128][72]

    int tid = threadIdx.x, lane = tid & 31, wid = tid >> 5;
    int qt = 7 - (int)blockIdx.x;      // longest first
    int h  = blockIdx.y;
    int zb = blockIdx.z;
    int s = zb >> 2, b = zb & 3;
    int rbase = s * NT + b * TT;
    const __half* qsrc  = g_qh + (size_t)(rbase + qt * 128) * CC + h * 64;
    const __half* ksrc  = g_kh + (size_t)(b * TT) * CC + h * 64;
    const __half* vtsrc = g_vTh + (size_t)(b * 16 + h) * 64 * TT;

    uint32_t sQ = smem_u32(Qs), sK = smem_u32(Kb), sV = smem_u32(Vb), sP = smem_u32(Ps);

    int ktmax = 2 * qt + 1;

    // one group = K(kt) + V(kt) into buffer kt%3
    auto issue = [&](int kt) {
        int buf = kt % 3;
        uint32_t kb = sK + (uint32_t)(buf * ATL) * 2;
        uint32_t vb = sV + (uint32_t)(buf * ATL) * 2;
        const __half* src = ksrc + (size_t)(kt * 64) * CC;
#pragma unroll
        for (int j = 0; j < 2; j++) {
            int lin = tid + j * 256;          // 512 cp16
            int r = lin >> 3, g = lin & 7;
            cp16(kb + (uint32_t)(r * HST + g * 8) * 2, src + (size_t)r * CC + g * 8);
        }
#pragma unroll
        for (int j = 0; j < 2; j++) {
            int lin = tid + j * 256;
            int d = lin >> 3, g = lin & 7;
            cp16(vb + (uint32_t)(d * HST + g * 8) * 2,
                 vtsrc + (size_t)d * TT + kt * 64 + g * 8);
        }
        CP_COMMIT();
    };

    // prologue: G0 = Q + K0 + V0 ; G1 = K1 + V1
    {
#pragma unroll
        for (int j = 0; j < 4; j++) {
            int lin = tid + j * 256;          // 1024 cp16
            int r = lin >> 3, g = lin & 7;
            cp16(sQ + (uint32_t)(r * HST + g * 8) * 2, qsrc + (size_t)r * CC + g * 8);
        }
        issue(0);          // commits Q+K0+V0 together
        issue(1);          // ktmax >= 1 always
    }

    float Oa[8][4];
    float mrow[2], lrow[2];
#pragma unroll
    for (int nt = 0; nt < 8; nt++)
#pragma unroll
        for (int q = 0; q < 4; q++) Oa[nt][q] = 0.f;
    mrow[0] = mrow[1] = -1e30f;
    lrow[0] = lrow[1] = 0.f;

    int a_row = (lane & 7) + ((lane >> 3) & 1) * 8;
    int a_col = (lane >> 4) * 8;
    int b_row = (lane & 7) + (lane >> 4) * 8;
    int b_col = ((lane >> 3) & 1) * 8;

#pragma unroll 1
    for (int kt = 0; kt <= ktmax; kt++) {
        // exactly one newer group is always outstanding => WAIT1 guarantees group kt landed
        CP_WAIT1();
        __syncthreads();       // data visibility + all warps done with buffer (kt-1)%3
        if (kt + 2 <= ktmax) issue(kt + 2);   // into buffer (kt+2)%3 == (kt-1)%3 (free)
        else CP_COMMIT();                      // empty group keeps WAIT1 invariant

        uint32_t kbase = sK + (uint32_t)((kt % 3) * ATL) * 2;
        uint32_t vbase = sV + (uint32_t)((kt % 3) * ATL) * 2;

        // S = Q @ K^T  (warp rows: wid*16..+15)
        float sa[8][4];
#pragma unroll
        for (int nt = 0; nt < 8; nt++)
#pragma unroll
            for (int q = 0; q < 4; q++) sa[nt][q] = 0.f;
#pragma unroll
        for (int ks = 0; ks < 4; ks++) {
            int kc = ks * 16;
            uint32_t af[4];
            {
                int r = wid * 16 + a_row;
                ldsm4(af[0], af[1], af[2], af[3], sQ + (uint32_t)(r * HST + kc + a_col) * 2);
            }
#pragma unroll
            for (int p = 0; p < 4; p++) {
                int nr = p * 16 + b_row;
                uint32_t r0, r1, r2, r3;
                ldsm4(r0, r1, r2, r3, kbase + (uint32_t)(nr * HST + kc + b_col) * 2);
                uint32_t bf0[2] = { r0, r1 }, bf1[2] = { r2, r3 };
                mma_f16(sa[2 * p],     af, bf0);
                mma_f16(sa[2 * p + 1], af, bf1);
            }
        }

        // online softmax + P store (fp16)
        bool domask = (kt >= 2 * qt);
#pragma unroll
        for (int half = 0; half < 2; half++) {
            int rl = wid * 16 + (lane >> 2) + half * 8;
            int ig = qt * 128 + rl;
            float v[16];
#pragma unroll
            for (int nt = 0; nt < 8; nt++) {
                float s0 = sa[nt][half * 2 + 0] * 0.125f;
                float s1 = sa[nt][half * 2 + 1] * 0.125f;
                if (domask) {
                    int jg = kt * 64 + nt * 8 + 2 * (lane & 3);
                    if (jg > ig)     s0 = -1e30f;
                    if (jg + 1 > ig) s1 = -1e30f;
                }
                v[nt * 2] = s0; v[nt * 2 + 1] = s1;
            }
            float rm = v[0];
#pragma unroll
            for (int j = 1; j < 16; j++) rm = fmaxf(rm, v[j]);
            rm = fmaxf(rm, __shfl_xor_sync(0xFFFFFFFFu, rm, 1));
            rm = fmaxf(rm, __shfl_xor_sync(0xFFFFFFFFu, rm, 2));
            float mn = fmaxf(mrow[half], rm);
            float alpha = __expf(mrow[half] - mn);
            float rs = 0.f;
#pragma unroll
            for (int j = 0; j < 16; j++) { float p = __expf(v[j] - mn); v[j] = p; rs += p; }
            rs += __shfl_xor_sync(0xFFFFFFFFu, rs, 1);
            rs += __shfl_xor_sync(0xFFFFFFFFu, rs, 2);
            mrow[half] = mn;
            lrow[half] = lrow[half] * alpha + rs;
#pragma unroll
            for (int nt = 0; nt < 8; nt++) {
                Oa[nt][half * 2 + 0] *= alpha;
                Oa[nt][half * 2 + 1] *= alpha;
            }
            __half* pr = Ps + rl * HST;
#pragma unroll
            for (int nt = 0; nt < 8; nt++) {
                int j0 = nt * 8 + 2 * (lane & 3);
                *(__half2*)(pr + j0) = __floats2half2_rn(v[nt * 2], v[nt * 2 + 1]);
            }
        }
        __syncwarp();          // P band is warp-private

        // O += P @ V  (A = own 16-row band of Ps)
#pragma unroll
        for (int ks = 0; ks < 4; ks++) {
            int kc = ks * 16;
            uint32_t af[4];
            {
                int r = wid * 16 + a_row;
                ldsm4(af[0], af[1], af[2], af[3], sP + (uint32_t)(r * HST + kc + a_col) * 2);
            }
#pragma unroll
            for (int p = 0; p < 4; p++) {
                int nr = p * 16 + b_row;
                uint32_t r0, r1, r2, r3;
                ldsm4(r0, r1, r2, r3, vbase + (uint32_t)(nr * HST + kc + b_col) * 2);
                uint32_t bf0[2] = { r0, r1 }, bf1[2] = { r2, r3 };
                mma_f16(Oa[2 * p],     af, bf0);
                mma_f16(Oa[2 * p + 1], af, bf1);
            }
        }
    }

    // write O (fp16: pre-converts the o-GEMM A operand)
#pragma unroll
    for (int half = 0; half < 2; half++) {
        int rl = wid * 16 + (lane >> 2) + half * 8;
        float inv = 1.f / lrow[half];
        __half* orow = g_ath + (size_t)(rbase + qt * 128 + rl) * CC;
#pragma unroll
        for (int nt = 0; nt < 8; nt++) {
            int c0 = h * 64 + nt * 8 + 2 * (lane & 3);
            *(__half2*)(orow + c0) =
                __floats2half2_rn(Oa[nt][half * 2 + 0] * inv, Oa[nt][half * 2 + 1] * inv);
        }
    }
}

// ---------------- final combine (float4) ----------------
__global__ void combine(float* __restrict__ out)
{
    int i = blockIdx.x * 256 + threadIdx.x;   // over NT*CC/4 float4
    int token = i >> 8;
    float w0 = g_w[token], w1 = g_w[NT + token];
    float4 a = ((const float4*)g_o)[i];
    float4 b = ((const float4*)(g_o + (size_t)NT * CC))[i];
    float4 r;
    r.x = w0 * a.x + w1 * b.x;
    r.y = w0 * a.y + w1 * b.y;
    r.z = w0 * a.z + w1 * b.z;
    r.w = w0 * a.w + w1 * b.w;
    ((float4*)out)[i] = r;
}

// ---------------- launch ----------------
extern "C" void kernel_launch(void* const* d_in, const int* in_sizes, int n_in,
                              void* d_out, int out_size)
{
    const float* x     = (const float*)d_in[0];
    const float* noise = (const float*)d_in[1];
    const float* Wk    = (const float*)d_in[2];
    const float* Wv    = (const float*)d_in[3];
    const float* Wq    = (const float*)d_in[4];
    const float* Wo    = (const float*)d_in[5];
    const float* Wg    = (const float*)d_in[6];
    const float* Wn    = (const float*)d_in[7];
    float* out = (float*)d_out;

    const int gemm_smem = 6 * HGS * 2;                      // 110592
    const int attn_smem = (128 * HST + 6 * ATL + 128 * HST) * 2;  // 92160
    cudaFuncSetAttribute(gemm_h, cudaFuncAttributeMaxDynamicSharedMemorySize, gemm_smem);
    cudaFuncSetAttribute(attn_h, cudaFuncAttributeMaxDynamicSharedMemorySize, attn_smem);

    zero_cnt<<<1, 32>>>();
    gate_kernel<<<NT, 256>>>(x, noise, Wg, Wn);
    prep_w<<<dim3(32, 32, 18), 256>>>(Wk, Wv, Wq, Wo);

    gemm_h<<<dim3(8, 32, 10), 256, gemm_smem>>>(0);    // k | v | q_sel (fused)

    transpose_v<<<dim3(32, 2, 64), 256>>>();

    attn_h<<<dim3(8, 16, 8), 256, attn_smem>>>();

    gemm_h<<<dim3(8, 32, 8), 256, gemm_smem>>>(2);     // o_sel

    combine<<<(NT * CC / 4) / 256, 256>>>(out);
}

// round 16
// speedup vs baseline: 2.2659x; 1.1595x over previous
#include <cuda_runtime.h>
#include <cuda_fp16.h>
#include <math.h>
#include <cstdint>

#define TT 1024
#define CC 1024
#define EE 8
#define NT 4096   // B*T tokens
#define NR 8192   // 2 slots * NT rows
#define MEG 1048576

// ---------------- scratch (device globals; no allocs allowed) ----------------
__device__ __half g_xh [(size_t)NT * CC];        // x, fp16
__device__ __half g_kh [(size_t)NT * CC];        // k, fp16
__device__ __half g_vh [(size_t)NT * CC];        // v, fp16
__device__ __half g_vTh[(size_t)64 * 64 * TT];   // [b*16+h][d][t], fp16
__device__ __half g_qh [(size_t)NR * CC];        // q gathered, fp16
__device__ __half g_ath[(size_t)NR * CC];        // attention out, fp16
__device__ float  g_o  [(size_t)NR * CC];        // o gathered, fp32
__device__ __half g_wt [(size_t)18 * MEG];       // transposed weights [z][n][k], fp16
__device__ float  g_w  [NR];
__device__ int    g_rl[EE][NT];
__device__ int    g_cnt[EE];

__global__ void zero_cnt() { if (threadIdx.x < EE) g_cnt[threadIdx.x] = 0; }

// ---------------- helpers ----------------
__device__ __forceinline__ uint32_t smem_u32(const void* p) {
    uint32_t a;
    asm("{ .reg .u64 t; cvta.to.shared.u64 t, %1; cvt.u32.u64 %0, t; }" : "=r"(a) : "l"(p));
    return a;
}
__device__ __forceinline__ uint32_t h2u(__half2 h) {
    return *reinterpret_cast<uint32_t*>(&h);
}
__device__ __forceinline__ float fast_ex2(float x) {
    float r;
    asm("ex2.approx.f32 %0, %1;" : "=f"(r) : "f"(x));
    return r;
}
__device__ __forceinline__ void ldsm4(uint32_t& r0, uint32_t& r1, uint32_t& r2, uint32_t& r3,
                                      uint32_t addr) {
    asm volatile("ldmatrix.sync.aligned.m8n8.x4.shared.b16 {%0,%1,%2,%3}, [%4];"
                 : "=r"(r0), "=r"(r1), "=r"(r2), "=r"(r3) : "r"(addr));
}
__device__ __forceinline__ void mma_f16(float* d, const uint32_t* a, const uint32_t* b) {
    asm volatile(
        "mma.sync.aligned.m16n8k16.row.col.f32.f16.f16.f32 "
        "{%0,%1,%2,%3},{%4,%5,%6,%7},{%8,%9},{%0,%1,%2,%3};"
        : "+f"(d[0]), "+f"(d[1]), "+f"(d[2]), "+f"(d[3])
        : "r"(a[0]), "r"(a[1]), "r"(a[2]), "r"(a[3]), "r"(b[0]), "r"(b[1]));
}
__device__ __forceinline__ void cp16(uint32_t dst, const void* src) {
    asm volatile("cp.async.ca.shared.global [%0], [%1], 16;" :: "r"(dst), "l"(src) : "memory");
}
#define CP_COMMIT() asm volatile("cp.async.commit_group;" ::: "memory")
#define CP_WAIT1()  asm volatile("cp.async.wait_group 1;" ::: "memory")

// ---------------- gating (+ fused x -> fp16) ----------------
__global__ __launch_bounds__(256) void gate_kernel(
    const float* __restrict__ x, const float* __restrict__ noise,
    const float* __restrict__ Wg, const float* __restrict__ Wn)
{
    int row = blockIdx.x;
    int tid = threadIdx.x;
    const float* xr = x + (size_t)row * CC;

    float accg[8], accn[8];
#pragma unroll
    for (int e = 0; e < 8; e++) { accg[e] = 0.f; accn[e] = 0.f; }
    for (int c = tid; c < CC; c += 256) {
        float xv = xr[c];
        const float* wg = Wg + c * 8;
        const float* wn = Wn + c * 8;
#pragma unroll
        for (int e = 0; e < 8; e++) { accg[e] += xv * wg[e]; accn[e] += xv * wn[e]; }
    }
    __shared__ float red[16][256];
#pragma unroll
    for (int e = 0; e < 8; e++) { red[e][tid] = accg[e]; red[8 + e][tid] = accn[e]; }
    __syncthreads();
    // tree reduction over the 256-thread axis
#pragma unroll
    for (int s = 128; s > 0; s >>= 1) {
        if (tid < s) {
#pragma unroll
            for (int e = 0; e < 16; e++) red[e][tid] += red[e][tid + s];
        }
        __syncthreads();
    }
    // fused: x row -> fp16 (L1-hot)
    {
        int c = tid * 4;
        float4 vv = *(const float4*)(xr + c);
        __half2* dst = (__half2*)(g_xh + (size_t)row * CC + c);
        dst[0] = __floats2half2_rn(vv.x, vv.y);
        dst[1] = __floats2half2_rn(vv.z, vv.w);
    }
    if (tid == 0) {
        float logit[8];
#pragma unroll
        for (int e = 0; e < 8; e++) {
            float z  = red[8 + e][0];
            float sp = (z > 20.f) ? z : log1pf(expf(z));
            logit[e] = red[e][0] + noise[row * 8 + e] * sp;
        }
        int i0 = 0; float v0 = logit[0];
#pragma unroll
        for (int e = 1; e < 8; e++) if (logit[e] > v0) { v0 = logit[e]; i0 = e; }
        int i1 = -1; float v1 = -INFINITY;
#pragma unroll
        for (int e = 0; e < 8; e++) if (e != i0 && logit[e] > v1) { v1 = logit[e]; i1 = e; }
        float p1 = 1.f / (1.f + expf(v0 - v1));
        float p0 = 1.f - p1;
        g_w[row]      = p0;
        g_w[NT + row] = p1;
        int pos0 = atomicAdd(&g_cnt[i0], 1); g_rl[i0][pos0] = row;
        int pos1 = atomicAdd(&g_cnt[i1], 1); g_rl[i1][pos1] = NT + row;
    }
}

// ---------------- weight prep: transpose [k][n] -> [n][k], fp16 ----------------
// z: 0=Wk, 1=Wv, 2..9=Wq[e], 10..17=Wo[e]
__global__ __launch_bounds__(256) void prep_w(
    const float* __restrict__ Wk, const float* __restrict__ Wv,
    const float* __restrict__ Wq, const float* __restrict__ Wo)
{
    __shared__ float tile[32][33];
    int z = blockIdx.z;
    const float* src = (z == 0) ? Wk : (z == 1) ? Wv :
                       (z < 10) ? Wq + (size_t)(z - 2) * MEG : Wo + (size_t)(z - 10) * MEG;
    __half* dst = g_wt + (size_t)z * MEG;
    int k0 = blockIdx.y * 32, n0 = blockIdx.x * 32;
    int tx = threadIdx.x & 31, ty = threadIdx.x >> 5;
#pragma unroll
    for (int r = 0; r < 4; r++)
        tile[ty + r * 8][tx] = src[(size_t)(k0 + ty + r * 8) * CC + n0 + tx];
    __syncthreads();
#pragma unroll
    for (int r = 0; r < 4; r++)
        dst[(size_t)(n0 + ty + r * 8) * CC + k0 + tx] = __float2half_rn(tile[tx][ty + r * 8]);
}

// ---------------- V transpose per (b,h): [t][d] -> [d][t], fp16 ----------------
__global__ __launch_bounds__(256) void transpose_v()
{
    __shared__ float tile[32][33];
    int bh = blockIdx.z;
    int b = bh >> 4, h = bh & 15;
    int t0 = blockIdx.x * 32, d0 = blockIdx.y * 32;
    int tx = threadIdx.x & 31, ty = threadIdx.x >> 5;
#pragma unroll
    for (int r = 0; r < 4; r++)
        tile[ty + r * 8][tx] =
            __half2float(g_vh[(size_t)(b * TT + t0 + ty + r * 8) * CC + h * 64 + d0 + tx]);
    __syncthreads();
#pragma unroll
    for (int r = 0; r < 4; r++)
        g_vTh[((size_t)bh * 64 + d0 + ty + r * 8) * TT + t0 + tx] =
            __float2half_rn(tile[tx][ty + r * 8]);
}

// ---------------- fp16 mma GEMM: 256 thr, 8 warps x (64x32), K chunk 64, 3-stage ----------------
// mode 0: z 0..9 (z<2: dense k/v; z>=2: gather-q for expert z-2)
// mode 2: z 0..7 (gather-o for expert z), fp32 output
#define HST 72            // halfs per stage row
#define HGS (128 * HST)   // halfs per stage (A or B)
__global__ __launch_bounds__(256) void gemm_h(int mode)
{
    extern __shared__ __half smh[];
    __half* As = smh;                 // [3][128][72]
    __half* Bs = smh + 3 * HGS;       // [3][128][72]
    __shared__ int s_src[128];
    __shared__ int s_dst[128];

    int tid = threadIdx.x, lane = tid & 31, wid = tid >> 5;
    int z = blockIdx.z, row0 = blockIdx.y * 128, n0 = blockIdx.x * 128;

    const __half* Ag;
    const __half* Bw;
    __half* Ch = nullptr;
    float*  Cf = nullptr;
    int cnt = NT, e = 0;
    bool gather;
    if (mode == 0) {
        Ag = g_xh;
        Bw = g_wt + (size_t)z * MEG;
        if (z < 2) { Ch = z ? g_vh : g_kh; gather = false; }
        else {
            e = z - 2; Ch = g_qh; gather = true;
            cnt = g_cnt[e];
            if (row0 >= cnt) return;
        }
    } else {
        e = z; Ag = g_ath;
        Bw = g_wt + (size_t)(10 + z) * MEG;
        Cf = g_o; gather = true;
        cnt = g_cnt[e];
        if (row0 >= cnt) return;
    }
    if (tid < 128) {
        int gr = row0 + tid;
        if (!gather) { s_src[tid] = gr; s_dst[tid] = gr; }
        else if (gr < cnt) {
            int r = g_rl[e][gr];
            s_src[tid] = (mode == 0) ? (r & (NT - 1)) : r;
            s_dst[tid] = r;
        } else { s_src[tid] = 0; s_dst[tid] = -1; }
    }
    __syncthreads();

    uint32_t sA = smem_u32(As), sB = smem_u32(Bs);
    const __half* aptr[4];
    const __half* bptr[4];
    uint32_t adst[4], bdst[4];
#pragma unroll
    for (int j = 0; j < 4; j++) {
        int lin = tid + j * 256;          // 0..1023
        int r = lin >> 3, g = lin & 7;    // 8 halfs = 16 B per cp
        aptr[j] = Ag + (size_t)s_src[r] * CC + g * 8;
        adst[j] = sA + (uint32_t)(r * HST + g * 8) * 2;
        bptr[j] = Bw + (size_t)(n0 + r) * CC + g * 8;
        bdst[j] = sB + (uint32_t)(r * HST + g * 8) * 2;
    }
    auto issue = [&](int c, int stg) {
        uint32_t off = (uint32_t)stg * HGS * 2;
#pragma unroll
        for (int j = 0; j < 4; j++) cp16(adst[j] + off, aptr[j] + c * 64);
#pragma unroll
        for (int j = 0; j < 4; j++) cp16(bdst[j] + off, bptr[j] + c * 64);
        CP_COMMIT();
    };

    float acc[4][4][4];
#pragma unroll
    for (int mt = 0; mt < 4; mt++)
#pragma unroll
        for (int nt = 0; nt < 4; nt++)
#pragma unroll
            for (int q = 0; q < 4; q++) acc[mt][nt][q] = 0.f;

    int wm = (wid >> 2) * 64;
    int wn = (wid & 3) * 32;
    // ldmatrix lane-address components
    int a_row = (lane & 7) + ((lane >> 3) & 1) * 8;   // + warp-tile row
    int a_col = (lane >> 4) * 8;                      // + kstep base
    int b_row = (lane & 7) + (lane >> 4) * 8;
    int b_col = ((lane >> 3) & 1) * 8;

    issue(0, 0); issue(1, 1);
#pragma unroll 1
    for (int c = 0; c < 16; c++) {
        int stg = c % 3;
        CP_WAIT1();
        __syncthreads();
        if (c + 2 < 16) issue(c + 2, (c + 2) % 3);
        uint32_t abase = sA + (uint32_t)stg * HGS * 2;
        uint32_t bbase = sB + (uint32_t)stg * HGS * 2;
#pragma unroll
        for (int ks = 0; ks < 4; ks++) {
            int kc = ks * 16;
            uint32_t af[4][4], bf[4][2];
#pragma unroll
            for (int mt = 0; mt < 4; mt++) {
                int r = wm + mt * 16 + a_row;
                ldsm4(af[mt][0], af[mt][1], af[mt][2], af[mt][3],
                      abase + (uint32_t)(r * HST + kc + a_col) * 2);
            }
#pragma unroll
            for (int p = 0; p < 2; p++) {
                int nr = wn + p * 16 + b_row;
                uint32_t r0, r1, r2, r3;
                ldsm4(r0, r1, r2, r3, bbase + (uint32_t)(nr * HST + kc + b_col) * 2);
                bf[2 * p][0] = r0; bf[2 * p][1] = r1;
                bf[2 * p + 1][0] = r2; bf[2 * p + 1][1] = r3;
            }
#pragma unroll
            for (int mt = 0; mt < 4; mt++)
#pragma unroll
                for (int nt = 0; nt < 4; nt++)
                    mma_f16(acc[mt][nt], af[mt], bf[nt]);
        }
    }

    int r0l = wm + (lane >> 2);
    int cb = n0 + wn + (lane & 3) * 2;
#pragma unroll
    for (int mt = 0; mt < 4; mt++) {
        int dA = s_dst[r0l + mt * 16];
        int dB = s_dst[r0l + mt * 16 + 8];
#pragma unroll
        for (int nt = 0; nt < 4; nt++) {
            int gc = cb + nt * 8;
            if (mode == 0) {
                if (dA >= 0)
                    *(__half2*)(Ch + (size_t)dA * CC + gc) =
                        __floats2half2_rn(acc[mt][nt][0], acc[mt][nt][1]);
                if (dB >= 0)
                    *(__half2*)(Ch + (size_t)dB * CC + gc) =
                        __floats2half2_rn(acc[mt][nt][2], acc[mt][nt][3]);
            } else {
                if (dA >= 0)
                    *(float2*)(Cf + (size_t)dA * CC + gc) = make_float2(acc[mt][nt][0], acc[mt][nt][1]);
                if (dB >= 0)
                    *(float2*)(Cf + (size_t)dB * CC + gc) = make_float2(acc[mt][nt][2], acc[mt][nt][3]);
            }
        }
    }
}

// ---------------- flash attention: P kept in registers, Q frags hoisted ----------------
// grid (8 qtiles, 16 heads, 8 = slot*4+b), 256 thr = 8 warps x 16 rows
#define ATL (64 * HST)    // halfs per K or V buffer
#define SCL 0.1803368801111244f   // 0.125 * log2(e)
__global__ __launch_bounds__(256, 2) void attn_h()
{
    extern __shared__ __half smh[];
    __half* Qs = smh;                  // [128][72]
    __half* Kb = smh + 128 * HST;      // [3][64][72]
    __half* Vb = Kb + 3 * ATL;         // [3][64 d][72 j]

    int tid = threadIdx.x, lane = tid & 31, wid = tid >> 5;
    int qt = 7 - (int)blockIdx.x;      // longest first
    int h  = blockIdx.y;
    int zb = blockIdx.z;
    int s = zb >> 2, b = zb & 3;
    int rbase = s * NT + b * TT;
    const __half* qsrc  = g_qh + (size_t)(rbase + qt * 128) * CC + h * 64;
    const __half* ksrc  = g_kh + (size_t)(b * TT) * CC + h * 64;
    const __half* vtsrc = g_vTh + (size_t)(b * 16 + h) * 64 * TT;

    uint32_t sQ = smem_u32(Qs), sK = smem_u32(Kb), sV = smem_u32(Vb);

    int ktmax = 2 * qt + 1;

    // one group = K(kt) + V(kt) into buffer kt%3
    auto issue = [&](int kt) {
        int buf = kt % 3;
        uint32_t kb = sK + (uint32_t)(buf * ATL) * 2;
        uint32_t vb = sV + (uint32_t)(buf * ATL) * 2;
        const __half* src = ksrc + (size_t)(kt * 64) * CC;
#pragma unroll
        for (int j = 0; j < 2; j++) {
            int lin = tid + j * 256;          // 512 cp16
            int r = lin >> 3, g = lin & 7;
            cp16(kb + (uint32_t)(r * HST + g * 8) * 2, src + (size_t)r * CC + g * 8);
        }
#pragma unroll
        for (int j = 0; j < 2; j++) {
            int lin = tid + j * 256;
            int d = lin >> 3, g = lin & 7;
            cp16(vb + (uint32_t)(d * HST + g * 8) * 2,
                 vtsrc + (size_t)d * TT + kt * 64 + g * 8);
        }
        CP_COMMIT();
    };

    // prologue: G0 = Q + K0 + V0 ; G1 = K1 + V1
    {
#pragma unroll
        for (int j = 0; j < 4; j++) {
            int lin = tid + j * 256;          // 1024 cp16
            int r = lin >> 3, g = lin & 7;
            cp16(sQ + (uint32_t)(r * HST + g * 8) * 2, qsrc + (size_t)r * CC + g * 8);
        }
        issue(0);          // commits Q+K0+V0 together
        issue(1);          // ktmax >= 1 always
    }

    float Oa[8][4];
    float mrow[2], lrow[2];
#pragma unroll
    for (int nt = 0; nt < 8; nt++)
#pragma unroll
        for (int q = 0; q < 4; q++) Oa[nt][q] = 0.f;
    mrow[0] = mrow[1] = -1e30f;
    lrow[0] = lrow[1] = 0.f;

    int a_row = (lane & 7) + ((lane >> 3) & 1) * 8;
    int a_col = (lane >> 4) * 8;
    int b_row = (lane & 7) + (lane >> 4) * 8;
    int b_col = ((lane >> 3) & 1) * 8;

    uint32_t qf[4][4];     // Q fragments, loop-invariant

#pragma unroll 1
    for (int kt = 0; kt <= ktmax; kt++) {
        // exactly one newer group is always outstanding => WAIT1 guarantees group kt landed
        CP_WAIT1();
        __syncthreads();       // data visibility + all warps done with buffer (kt-1)%3
        if (kt + 2 <= ktmax) issue(kt + 2);   // into buffer (kt+2)%3 == (kt-1)%3 (free)
        else CP_COMMIT();                      // empty group keeps WAIT1 invariant

        if (kt == 0) {         // hoist Q fragments (Q landed with group 0)
            int r = wid * 16 + a_row;
#pragma unroll
            for (int ks = 0; ks < 4; ks++)
                ldsm4(qf[ks][0], qf[ks][1], qf[ks][2], qf[ks][3],
                      sQ + (uint32_t)(r * HST + ks * 16 + a_col) * 2);
        }

        uint32_t kbase = sK + (uint32_t)((kt % 3) * ATL) * 2;
        uint32_t vbase = sV + (uint32_t)((kt % 3) * ATL) * 2;

        // S = Q @ K^T  (warp rows: wid*16..+15)
        float sa[8][4];
#pragma unroll
        for (int nt = 0; nt < 8; nt++)
#pragma unroll
            for (int q = 0; q < 4; q++) sa[nt][q] = 0.f;
#pragma unroll
        for (int ks = 0; ks < 4; ks++) {
            int kc = ks * 16;
#pragma unroll
            for (int p = 0; p < 4; p++) {
                int nr = p * 16 + b_row;
                uint32_t r0, r1, r2, r3;
                ldsm4(r0, r1, r2, r3, kbase + (uint32_t)(nr * HST + kc + b_col) * 2);
                uint32_t bf0[2] = { r0, r1 }, bf1[2] = { r2, r3 };
                mma_f16(sa[2 * p],     qf[ks], bf0);
                mma_f16(sa[2 * p + 1], qf[ks], bf1);
            }
        }

        // online softmax (exp2 domain); pack P directly into A-fragment half2 regs
        bool domask = (kt >= 2 * qt);
        uint32_t ph[2][8];
#pragma unroll
        for (int half = 0; half < 2; half++) {
            int rl = wid * 16 + (lane >> 2) + half * 8;
            int ig = qt * 128 + rl;
            float v[16];
#pragma unroll
            for (int nt = 0; nt < 8; nt++) {
                float s0 = sa[nt][half * 2 + 0] * SCL;
                float s1 = sa[nt][half * 2 + 1] * SCL;
                if (domask) {
                    int jg = kt * 64 + nt * 8 + 2 * (lane & 3);
                    if (jg > ig)     s0 = -1e30f;
                    if (jg + 1 > ig) s1 = -1e30f;
                }
                v[nt * 2] = s0; v[nt * 2 + 1] = s1;
            }
            float rm = v[0];
#pragma unroll
            for (int j = 1; j < 16; j++) rm = fmaxf(rm, v[j]);
            rm = fmaxf(rm, __shfl_xor_sync(0xFFFFFFFFu, rm, 1));
            rm = fmaxf(rm, __shfl_xor_sync(0xFFFFFFFFu, rm, 2));
            float mn = fmaxf(mrow[half], rm);
            float alpha = fast_ex2(mrow[half] - mn);
            float rs = 0.f;
#pragma unroll
            for (int j = 0; j < 16; j++) { float p = fast_ex2(v[j] - mn); v[j] = p; rs += p; }
            rs += __shfl_xor_sync(0xFFFFFFFFu, rs, 1);
            rs += __shfl_xor_sync(0xFFFFFFFFu, rs, 2);
            mrow[half] = mn;
            lrow[half] = lrow[half] * alpha + rs;
#pragma unroll
            for (int nt = 0; nt < 8; nt++) {
                Oa[nt][half * 2 + 0] *= alpha;
                Oa[nt][half * 2 + 1] *= alpha;
                ph[half][nt] = h2u(__floats2half2_rn(v[nt * 2], v[nt * 2 + 1]));
            }
        }

        // O += P @ V : S-accumulator layout == PV A-fragment layout (no smem round-trip)
#pragma unroll
        for (int ks = 0; ks < 4; ks++) {
            int kc = ks * 16;
            uint32_t af[4] = { ph[0][2 * ks], ph[1][2 * ks],
                               ph[0][2 * ks + 1], ph[1][2 * ks + 1] };
#pragma unroll
            for (int p = 0; p < 4; p++) {
                int nr = p * 16 + b_row;
                uint32_t r0, r1, r2, r3;
                ldsm4(r0, r1, r2, r3, vbase + (uint32_t)(nr * HST + kc + b_col) * 2);
                uint32_t bf0[2] = { r0, r1 }, bf1[2] = { r2, r3 };
                mma_f16(Oa[2 * p],     af, bf0);
                mma_f16(Oa[2 * p + 1], af, bf1);
            }
        }
    }

    // write O (fp16: pre-converts the o-GEMM A operand)
#pragma unroll
    for (int half = 0; half < 2; half++) {
        int rl = wid * 16 + (lane >> 2) + half * 8;
        float inv = 1.f / lrow[half];
        __half* orow = g_ath + (size_t)(rbase + qt * 128 + rl) * CC;
#pragma unroll
        for (int nt = 0; nt < 8; nt++) {
            int c0 = h * 64 + nt * 8 + 2 * (lane & 3);
            *(__half2*)(orow + c0) =
                __floats2half2_rn(Oa[nt][half * 2 + 0] * inv, Oa[nt][half * 2 + 1] * inv);
        }
    }
}

// ---------------- final combine (float4) ----------------
__global__ void combine(float* __restrict__ out)
{
    int i = blockIdx.x * 256 + threadIdx.x;   // over NT*CC/4 float4
    int token = i >> 8;
    float w0 = g_w[token], w1 = g_w[NT + token];
    float4 a = ((const float4*)g_o)[i];
    float4 b = ((const float4*)(g_o + (size_t)NT * CC))[i];
    float4 r;
    r.x = w0 * a.x + w1 * b.x;
    r.y = w0 * a.y + w1 * b.y;
    r.z = w0 * a.z + w1 * b.z;
    r.w = w0 * a.w + w1 * b.w;
    ((float4*)out)[i] = r;
}

// ---------------- launch ----------------
extern "C" void kernel_launch(void* const* d_in, const int* in_sizes, int n_in,
                              void* d_out, int out_size)
{
    const float* x     = (const float*)d_in[0];
    const float* noise = (const float*)d_in[1];
    const float* Wk    = (const float*)d_in[2];
    const float* Wv    = (const float*)d_in[3];
    const float* Wq    = (const float*)d_in[4];
    const float* Wo    = (const float*)d_in[5];
    const float* Wg    = (const float*)d_in[6];
    const float* Wn    = (const float*)d_in[7];
    float* out = (float*)d_out;

    const int gemm_smem = 6 * HGS * 2;                      // 110592
    const int attn_smem = (128 * HST + 6 * ATL) * 2;        // 73728
    cudaFuncSetAttribute(gemm_h, cudaFuncAttributeMaxDynamicSharedMemorySize, gemm_smem);
    cudaFuncSetAttribute(attn_h, cudaFuncAttributeMaxDynamicSharedMemorySize, attn_smem);

    zero_cnt<<<1, 32>>>();
    gate_kernel<<<NT, 256>>>(x, noise, Wg, Wn);
    prep_w<<<dim3(32, 32, 18), 256>>>(Wk, Wv, Wq, Wo);

    gemm_h<<<dim3(8, 32, 10), 256, gemm_smem>>>(0);    // k | v | q_sel (fused)

    transpose_v<<<dim3(32, 2, 64), 256>>>();

    attn_h<<<dim3(8, 16, 8), 256, attn_smem>>>();

    gemm_h<<<dim3(8, 32, 8), 256, gemm_smem>>>(2);     // o_sel

    combine<<<(NT * CC / 4) / 256, 256>>>(out);
}

// round 17
// speedup vs baseline: 2.2974x; 1.0139x over previous
#include <cuda_runtime.h>
#include <cuda_fp16.h>
#include <math.h>
#include <cstdint>

#define TT 1024
#define CC 1024
#define EE 8
#define NT 4096   // B*T tokens
#define NR 8192   // 2 slots * NT rows
#define MEG 1048576

// ---------------- scratch (device globals; no allocs allowed) ----------------
__device__ __half g_xh [(size_t)NT * CC];        // x, fp16
__device__ __half g_kh [(size_t)NT * CC];        // k, fp16
__device__ __half g_vh [(size_t)NT * CC];        // v, fp16
__device__ __half g_vTh[(size_t)64 * 64 * TT];   // [b*16+h][d][t], fp16
__device__ __half g_qh [(size_t)NR * CC];        // q gathered, fp16
__device__ __half g_ath[(size_t)NR * CC];        // attention out, fp16
__device__ float  g_o  [(size_t)NR * CC];        // o gathered, fp32
__device__ __half g_wt [(size_t)18 * MEG];       // transposed weights [z][n][k], fp16
__device__ float  g_w  [NR];
__device__ int    g_rl[EE][NT];
__device__ int    g_cnt[EE];

__global__ void zero_cnt() { if (threadIdx.x < EE) g_cnt[threadIdx.x] = 0; }

// ---------------- helpers ----------------
__device__ __forceinline__ uint32_t smem_u32(const void* p) {
    uint32_t a;
    asm("{ .reg .u64 t; cvta.to.shared.u64 t, %1; cvt.u32.u64 %0, t; }" : "=r"(a) : "l"(p));
    return a;
}
__device__ __forceinline__ uint32_t h2u(__half2 h) {
    return *reinterpret_cast<uint32_t*>(&h);
}
__device__ __forceinline__ float fast_ex2(float x) {
    float r;
    asm("ex2.approx.f32 %0, %1;" : "=f"(r) : "f"(x));
    return r;
}
__device__ __forceinline__ void ldsm4(uint32_t& r0, uint32_t& r1, uint32_t& r2, uint32_t& r3,
                                      uint32_t addr) {
    asm volatile("ldmatrix.sync.aligned.m8n8.x4.shared.b16 {%0,%1,%2,%3}, [%4];"
                 : "=r"(r0), "=r"(r1), "=r"(r2), "=r"(r3) : "r"(addr));
}
__device__ __forceinline__ void mma_f16(float* d, const uint32_t* a, const uint32_t* b) {
    asm volatile(
        "mma.sync.aligned.m16n8k16.row.col.f32.f16.f16.f32 "
        "{%0,%1,%2,%3},{%4,%5,%6,%7},{%8,%9},{%0,%1,%2,%3};"
        : "+f"(d[0]), "+f"(d[1]), "+f"(d[2]), "+f"(d[3])
        : "r"(a[0]), "r"(a[1]), "r"(a[2]), "r"(a[3]), "r"(b[0]), "r"(b[1]));
}
__device__ __forceinline__ void cp16(uint32_t dst, const void* src) {
    asm volatile("cp.async.ca.shared.global [%0], [%1], 16;" :: "r"(dst), "l"(src) : "memory");
}
#define CP_COMMIT() asm volatile("cp.async.commit_group;" ::: "memory")
#define CP_WAIT1()  asm volatile("cp.async.wait_group 1;" ::: "memory")

// ---------------- gating (+ fused x -> fp16) ----------------
__global__ __launch_bounds__(256) void gate_kernel(
    const float* __restrict__ x, const float* __restrict__ noise,
    const float* __restrict__ Wg, const float* __restrict__ Wn)
{
    int row = blockIdx.x;
    int tid = threadIdx.x;
    const float* xr = x + (size_t)row * CC;

    float accg[8], accn[8];
#pragma unroll
    for (int e = 0; e < 8; e++) { accg[e] = 0.f; accn[e] = 0.f; }
    for (int c = tid; c < CC; c += 256) {
        float xv = xr[c];
        const float* wg = Wg + c * 8;
        const float* wn = Wn + c * 8;
#pragma unroll
        for (int e = 0; e < 8; e++) { accg[e] += xv * wg[e]; accn[e] += xv * wn[e]; }
    }
    __shared__ float red[16][256];
#pragma unroll
    for (int e = 0; e < 8; e++) { red[e][tid] = accg[e]; red[8 + e][tid] = accn[e]; }
    __syncthreads();
    // tree reduction over the 256-thread axis
#pragma unroll
    for (int s = 128; s > 0; s >>= 1) {
        if (tid < s) {
#pragma unroll
            for (int e = 0; e < 16; e++) red[e][tid] += red[e][tid + s];
        }
        __syncthreads();
    }
    // fused: x row -> fp16 (L1-hot)
    {
        int c = tid * 4;
        float4 vv = *(const float4*)(xr + c);
        __half2* dst = (__half2*)(g_xh + (size_t)row * CC + c);
        dst[0] = __floats2half2_rn(vv.x, vv.y);
        dst[1] = __floats2half2_rn(vv.z, vv.w);
    }
    if (tid == 0) {
        float logit[8];
#pragma unroll
        for (int e = 0; e < 8; e++) {
            float z  = red[8 + e][0];
            float sp = (z > 20.f) ? z : log1pf(expf(z));
            logit[e] = red[e][0] + noise[row * 8 + e] * sp;
        }
        int i0 = 0; float v0 = logit[0];
#pragma unroll
        for (int e = 1; e < 8; e++) if (logit[e] > v0) { v0 = logit[e]; i0 = e; }
        int i1 = -1; float v1 = -INFINITY;
#pragma unroll
        for (int e = 0; e < 8; e++) if (e != i0 && logit[e] > v1) { v1 = logit[e]; i1 = e; }
        float p1 = 1.f / (1.f + expf(v0 - v1));
        float p0 = 1.f - p1;
        g_w[row]      = p0;
        g_w[NT + row] = p1;
        int pos0 = atomicAdd(&g_cnt[i0], 1); g_rl[i0][pos0] = row;
        int pos1 = atomicAdd(&g_cnt[i1], 1); g_rl[i1][pos1] = NT + row;
    }
}

// ---------------- weight prep: transpose [k][n] -> [n][k], fp16 ----------------
// z: 0=Wk, 1=Wv, 2..9=Wq[e], 10..17=Wo[e]
__global__ __launch_bounds__(256) void prep_w(
    const float* __restrict__ Wk, const float* __restrict__ Wv,
    const float* __restrict__ Wq, const float* __restrict__ Wo)
{
    __shared__ float tile[32][33];
    int z = blockIdx.z;
    const float* src = (z == 0) ? Wk : (z == 1) ? Wv :
                       (z < 10) ? Wq + (size_t)(z - 2) * MEG : Wo + (size_t)(z - 10) * MEG;
    __half* dst = g_wt + (size_t)z * MEG;
    int k0 = blockIdx.y * 32, n0 = blockIdx.x * 32;
    int tx = threadIdx.x & 31, ty = threadIdx.x >> 5;
#pragma unroll
    for (int r = 0; r < 4; r++)
        tile[ty + r * 8][tx] = src[(size_t)(k0 + ty + r * 8) * CC + n0 + tx];
    __syncthreads();
#pragma unroll
    for (int r = 0; r < 4; r++)
        dst[(size_t)(n0 + ty + r * 8) * CC + k0 + tx] = __float2half_rn(tile[tx][ty + r * 8]);
}

// ---------------- V transpose per (b,h): [t][d] -> [d][t], fp16 ----------------
__global__ __launch_bounds__(256) void transpose_v()
{
    __shared__ float tile[32][33];
    int bh = blockIdx.z;
    int b = bh >> 4, h = bh & 15;
    int t0 = blockIdx.x * 32, d0 = blockIdx.y * 32;
    int tx = threadIdx.x & 31, ty = threadIdx.x >> 5;
#pragma unroll
    for (int r = 0; r < 4; r++)
        tile[ty + r * 8][tx] =
            __half2float(g_vh[(size_t)(b * TT + t0 + ty + r * 8) * CC + h * 64 + d0 + tx]);
    __syncthreads();
#pragma unroll
    for (int r = 0; r < 4; r++)
        g_vTh[((size_t)bh * 64 + d0 + ty + r * 8) * TT + t0 + tx] =
            __float2half_rn(tile[tx][ty + r * 8]);
}

// ---------------- fp16 mma GEMM: 128 thr, 4 warps x (64x64), K chunk 64, 3-stage ----------------
// mode 0: z 0..9 (z<2: dense k/v; z>=2: gather-q for expert z-2)
// mode 2: z 0..7 (gather-o for expert z), fp32 output
#define HST 72            // halfs per stage row
#define HGS (128 * HST)   // halfs per stage (A or B)
__global__ __launch_bounds__(128, 2) void gemm_h(int mode)
{
    extern __shared__ __half smh[];
    __half* As = smh;                 // [3][128][72]
    __half* Bs = smh + 3 * HGS;       // [3][128][72]
    __shared__ int s_src[128];
    __shared__ int s_dst[128];

    int tid = threadIdx.x, lane = tid & 31, wid = tid >> 5;   // wid 0..3
    int z = blockIdx.z, row0 = blockIdx.y * 128, n0 = blockIdx.x * 128;

    const __half* Ag;
    const __half* Bw;
    __half* Ch = nullptr;
    float*  Cf = nullptr;
    int cnt = NT, e = 0;
    bool gather;
    if (mode == 0) {
        Ag = g_xh;
        Bw = g_wt + (size_t)z * MEG;
        if (z < 2) { Ch = z ? g_vh : g_kh; gather = false; }
        else {
            e = z - 2; Ch = g_qh; gather = true;
            cnt = g_cnt[e];
            if (row0 >= cnt) return;
        }
    } else {
        e = z; Ag = g_ath;
        Bw = g_wt + (size_t)(10 + z) * MEG;
        Cf = g_o; gather = true;
        cnt = g_cnt[e];
        if (row0 >= cnt) return;
    }
    {
        int gr = row0 + tid;
        if (!gather) { s_src[tid] = gr; s_dst[tid] = gr; }
        else if (gr < cnt) {
            int r = g_rl[e][gr];
            s_src[tid] = (mode == 0) ? (r & (NT - 1)) : r;
            s_dst[tid] = r;
        } else { s_src[tid] = 0; s_dst[tid] = -1; }
    }
    __syncthreads();

    uint32_t sA = smem_u32(As), sB = smem_u32(Bs);
    // staging: 1024 cp16 per operand per chunk; thread does 8 each.
    // row r = (tid>>3) + j*16, group g = tid&7. adst stride per j = 16*HST*2 bytes.
    int srow = tid >> 3, sg = tid & 7;
    uint32_t adst0 = sA + (uint32_t)(srow * HST + sg * 8) * 2;
    uint32_t bdst0 = sB + (uint32_t)(srow * HST + sg * 8) * 2;
    const __half* agBase = Ag + sg * 8;
    const __half* bptr0 = Bw + (size_t)(n0 + srow) * CC + sg * 8;

    auto issue = [&](int c, int stg) {
        uint32_t off = (uint32_t)stg * HGS * 2;
#pragma unroll
        for (int j = 0; j < 8; j++) {
            int r = srow + j * 16;
            cp16(adst0 + off + (uint32_t)j * (16 * HST * 2),
                 agBase + (size_t)s_src[r] * CC + c * 64);
        }
#pragma unroll
        for (int j = 0; j < 8; j++)
            cp16(bdst0 + off + (uint32_t)j * (16 * HST * 2),
                 bptr0 + (size_t)j * 16 * CC + c * 64);
        CP_COMMIT();
    };

    float acc[4][8][4];
#pragma unroll
    for (int mt = 0; mt < 4; mt++)
#pragma unroll
        for (int nt = 0; nt < 8; nt++)
#pragma unroll
            for (int q = 0; q < 4; q++) acc[mt][nt][q] = 0.f;

    int wm = (wid >> 1) * 64;        // {0,64}
    int wn = (wid & 1) * 64;         // {0,64}
    // ldmatrix lane-address components
    int a_row = (lane & 7) + ((lane >> 3) & 1) * 8;   // + warp-tile row
    int a_col = (lane >> 4) * 8;                      // + kstep base
    int b_row = (lane & 7) + (lane >> 4) * 8;
    int b_col = ((lane >> 3) & 1) * 8;

    issue(0, 0); issue(1, 1);
#pragma unroll 1
    for (int c = 0; c < 16; c++) {
        int stg = c % 3;
        CP_WAIT1();
        __syncthreads();
        if (c + 2 < 16) issue(c + 2, (c + 2) % 3);
        uint32_t abase = sA + (uint32_t)stg * HGS * 2;
        uint32_t bbase = sB + (uint32_t)stg * HGS * 2;
#pragma unroll
        for (int ks = 0; ks < 4; ks++) {
            int kc = ks * 16;
            uint32_t af[4][4], bf[8][2];
#pragma unroll
            for (int mt = 0; mt < 4; mt++) {
                int r = wm + mt * 16 + a_row;
                ldsm4(af[mt][0], af[mt][1], af[mt][2], af[mt][3],
                      abase + (uint32_t)(r * HST + kc + a_col) * 2);
            }
#pragma unroll
            for (int p = 0; p < 4; p++) {
                int nr = wn + p * 16 + b_row;
                uint32_t r0, r1, r2, r3;
                ldsm4(r0, r1, r2, r3, bbase + (uint32_t)(nr * HST + kc + b_col) * 2);
                bf[2 * p][0] = r0; bf[2 * p][1] = r1;
                bf[2 * p + 1][0] = r2; bf[2 * p + 1][1] = r3;
            }
#pragma unroll
            for (int mt = 0; mt < 4; mt++)
#pragma unroll
                for (int nt = 0; nt < 8; nt++)
                    mma_f16(acc[mt][nt], af[mt], bf[nt]);
        }
    }

    int r0l = wm + (lane >> 2);
    int cb = n0 + wn + (lane & 3) * 2;
#pragma unroll
    for (int mt = 0; mt < 4; mt++) {
        int dA = s_dst[r0l + mt * 16];
        int dB = s_dst[r0l + mt * 16 + 8];
#pragma unroll
        for (int nt = 0; nt < 8; nt++) {
            int gc = cb + nt * 8;
            if (mode == 0) {
                if (dA >= 0)
                    *(__half2*)(Ch + (size_t)dA * CC + gc) =
                        __floats2half2_rn(acc[mt][nt][0], acc[mt][nt][1]);
                if (dB >= 0)
                    *(__half2*)(Ch + (size_t)dB * CC + gc) =
                        __floats2half2_rn(acc[mt][nt][2], acc[mt][nt][3]);
            } else {
                if (dA >= 0)
                    *(float2*)(Cf + (size_t)dA * CC + gc) = make_float2(acc[mt][nt][0], acc[mt][nt][1]);
                if (dB >= 0)
                    *(float2*)(Cf + (size_t)dB * CC + gc) = make_float2(acc[mt][nt][2], acc[mt][nt][3]);
            }
        }
    }
}

// ---------------- flash attention: P kept in registers, Q frags hoisted ----------------
// grid (8 qtiles, 16 heads, 8 = slot*4+b), 256 thr = 8 warps x 16 rows
#define ATL (64 * HST)    // halfs per K or V buffer
#define SCL 0.1803368801111244f   // 0.125 * log2(e)
__global__ __launch_bounds__(256, 2) void attn_h()
{
    extern __shared__ __half smh[];
    __half* Qs = smh;                  // [128][72]
    __half* Kb = smh + 128 * HST;      // [3][64][72]
    __half* Vb = Kb + 3 * ATL;         // [3][64 d][72 j]

    int tid = threadIdx.x, lane = tid & 31, wid = tid >> 5;
    int qt = 7 - (int)blockIdx.x;      // longest first
    int h  = blockIdx.y;
    int zb = blockIdx.z;
    int s = zb >> 2, b = zb & 3;
    int rbase = s * NT + b * TT;
    const __half* qsrc  = g_qh + (size_t)(rbase + qt * 128) * CC + h * 64;
    const __half* ksrc  = g_kh + (size_t)(b * TT) * CC + h * 64;
    const __half* vtsrc = g_vTh + (size_t)(b * 16 + h) * 64 * TT;

    uint32_t sQ = smem_u32(Qs), sK = smem_u32(Kb), sV = smem_u32(Vb);

    int ktmax = 2 * qt + 1;

    // one group = K(kt) + V(kt) into buffer kt%3
    auto issue = [&](int kt) {
        int buf = kt % 3;
        uint32_t kb = sK + (uint32_t)(buf * ATL) * 2;
        uint32_t vb = sV + (uint32_t)(buf * ATL) * 2;
        const __half* src = ksrc + (size_t)(kt * 64) * CC;
#pragma unroll
        for (int j = 0; j < 2; j++) {
            int lin = tid + j * 256;          // 512 cp16
            int r = lin >> 3, g = lin & 7;
            cp16(kb + (uint32_t)(r * HST + g * 8) * 2, src + (size_t)r * CC + g * 8);
        }
#pragma unroll
        for (int j = 0; j < 2; j++) {
            int lin = tid + j * 256;
            int d = lin >> 3, g = lin & 7;
            cp16(vb + (uint32_t)(d * HST + g * 8) * 2,
                 vtsrc + (size_t)d * TT + kt * 64 + g * 8);
        }
        CP_COMMIT();
    };

    // prologue: G0 = Q + K0 + V0 ; G1 = K1 + V1
    {
#pragma unroll
        for (int j = 0; j < 4; j++) {
            int lin = tid + j * 256;          // 1024 cp16
            int r = lin >> 3, g = lin & 7;
            cp16(sQ + (uint32_t)(r * HST + g * 8) * 2, qsrc + (size_t)r * CC + g * 8);
        }
        issue(0);          // commits Q+K0+V0 together
        issue(1);          // ktmax >= 1 always
    }

    float Oa[8][4];
    float mrow[2], lrow[2];
#pragma unroll
    for (int nt = 0; nt < 8; nt++)
#pragma unroll
        for (int q = 0; q < 4; q++) Oa[nt][q] = 0.f;
    mrow[0] = mrow[1] = -1e30f;
    lrow[0] = lrow[1] = 0.f;

    int a_row = (lane & 7) + ((lane >> 3) & 1) * 8;
    int a_col = (lane >> 4) * 8;
    int b_row = (lane & 7) + (lane >> 4) * 8;
    int b_col = ((lane >> 3) & 1) * 8;

    uint32_t qf[4][4];     // Q fragments, loop-invariant

#pragma unroll 1
    for (int kt = 0; kt <= ktmax; kt++) {
        // exactly one newer group is always outstanding => WAIT1 guarantees group kt landed
        CP_WAIT1();
        __syncthreads();       // data visibility + all warps done with buffer (kt-1)%3
        if (kt + 2 <= ktmax) issue(kt + 2);   // into buffer (kt+2)%3 == (kt-1)%3 (free)
        else CP_COMMIT();                      // empty group keeps WAIT1 invariant

        if (kt == 0) {         // hoist Q fragments (Q landed with group 0)
            int r = wid * 16 + a_row;
#pragma unroll
            for (int ks = 0; ks < 4; ks++)
                ldsm4(qf[ks][0], qf[ks][1], qf[ks][2], qf[ks][3],
                      sQ + (uint32_t)(r * HST + ks * 16 + a_col) * 2);
        }

        uint32_t kbase = sK + (uint32_t)((kt % 3) * ATL) * 2;
        uint32_t vbase = sV + (uint32_t)((kt % 3) * ATL) * 2;

        // S = Q @ K^T  (warp rows: wid*16..+15)
        float sa[8][4];
#pragma unroll
        for (int nt = 0; nt < 8; nt++)
#pragma unroll
            for (int q = 0; q < 4; q++) sa[nt][q] = 0.f;
#pragma unroll
        for (int ks = 0; ks < 4; ks++) {
            int kc = ks * 16;
#pragma unroll
            for (int p = 0; p < 4; p++) {
                int nr = p * 16 + b_row;
                uint32_t r0, r1, r2, r3;
                ldsm4(r0, r1, r2, r3, kbase + (uint32_t)(nr * HST + kc + b_col) * 2);
                uint32_t bf0[2] = { r0, r1 }, bf1[2] = { r2, r3 };
                mma_f16(sa[2 * p],     qf[ks], bf0);
                mma_f16(sa[2 * p + 1], qf[ks], bf1);
            }
        }

        // online softmax (exp2 domain); pack P directly into A-fragment half2 regs
        bool domask = (kt >= 2 * qt);
        uint32_t ph[2][8];
#pragma unroll
        for (int half = 0; half < 2; half++) {
            int rl = wid * 16 + (lane >> 2) + half * 8;
            int ig = qt * 128 + rl;
            float v[16];
#pragma unroll
            for (int nt = 0; nt < 8; nt++) {
                float s0 = sa[nt][half * 2 + 0] * SCL;
                float s1 = sa[nt][half * 2 + 1] * SCL;
                if (domask) {
                    int jg = kt * 64 + nt * 8 + 2 * (lane & 3);
                    if (jg > ig)     s0 = -1e30f;
                    if (jg + 1 > ig) s1 = -1e30f;
                }
                v[nt * 2] = s0; v[nt * 2 + 1] = s1;
            }
            float rm = v[0];
#pragma unroll
            for (int j = 1; j < 16; j++) rm = fmaxf(rm, v[j]);
            rm = fmaxf(rm, __shfl_xor_sync(0xFFFFFFFFu, rm, 1));
            rm = fmaxf(rm, __shfl_xor_sync(0xFFFFFFFFu, rm, 2));
            float mn = fmaxf(mrow[half], rm);
            float alpha = fast_ex2(mrow[half] - mn);
            float rs = 0.f;
#pragma unroll
            for (int j = 0; j < 16; j++) { float p = fast_ex2(v[j] - mn); v[j] = p; rs += p; }
            rs += __shfl_xor_sync(0xFFFFFFFFu, rs, 1);
            rs += __shfl_xor_sync(0xFFFFFFFFu, rs, 2);
            mrow[half] = mn;
            lrow[half] = lrow[half] * alpha + rs;
#pragma unroll
            for (int nt = 0; nt < 8; nt++) {
                Oa[nt][half * 2 + 0] *= alpha;
                Oa[nt][half * 2 + 1] *= alpha;
                ph[half][nt] = h2u(__floats2half2_rn(v[nt * 2], v[nt * 2 + 1]));
            }
        }

        // O += P @ V : S-accumulator layout == PV A-fragment layout (no smem round-trip)
#pragma unroll
        for (int ks = 0; ks < 4; ks++) {
            int kc = ks * 16;
            uint32_t af[4] = { ph[0][2 * ks], ph[1][2 * ks],
                               ph[0][2 * ks + 1], ph[1][2 * ks + 1] };
#pragma unroll
            for (int p = 0; p < 4; p++) {
                int nr = p * 16 + b_row;
                uint32_t r0, r1, r2, r3;
                ldsm4(r0, r1, r2, r3, vbase + (uint32_t)(nr * HST + kc + b_col) * 2);
                uint32_t bf0[2] = { r0, r1 }, bf1[2] = { r2, r3 };
                mma_f16(Oa[2 * p],     af, bf0);
                mma_f16(Oa[2 * p + 1], af, bf1);
            }
        }
    }

    // write O (fp16: pre-converts the o-GEMM A operand)
#pragma unroll
    for (int half = 0; half < 2; half++) {
        int rl = wid * 16 + (lane >> 2) + half * 8;
        float inv = 1.f / lrow[half];
        __half* orow = g_ath + (size_t)(rbase + qt * 128 + rl) * CC;
#pragma unroll
        for (int nt = 0; nt < 8; nt++) {
            int c0 = h * 64 + nt * 8 + 2 * (lane & 3);
            *(__half2*)(orow + c0) =
                __floats2half2_rn(Oa[nt][half * 2 + 0] * inv, Oa[nt][half * 2 + 1] * inv);
        }
    }
}

// ---------------- final combine (float4) ----------------
__global__ void combine(float* __restrict__ out)
{
    int i = blockIdx.x * 256 + threadIdx.x;   // over NT*CC/4 float4
    int token = i >> 8;
    float w0 = g_w[token], w1 = g_w[NT + token];
    float4 a = ((const float4*)g_o)[i];
    float4 b = ((const float4*)(g_o + (size_t)NT * CC))[i];
    float4 r;
    r.x = w0 * a.x + w1 * b.x;
    r.y = w0 * a.y + w1 * b.y;
    r.z = w0 * a.z + w1 * b.z;
    r.w = w0 * a.w + w1 * b.w;
    ((float4*)out)[i] = r;
}

// ---------------- launch ----------------
extern "C" void kernel_launch(void* const* d_in, const int* in_sizes, int n_in,
                              void* d_out, int out_size)
{
    const float* x     = (const float*)d_in[0];
    const float* noise = (const float*)d_in[1];
    const float* Wk    = (const float*)d_in[2];
    const float* Wv    = (const float*)d_in[3];
    const float* Wq    = (const float*)d_in[4];
    const float* Wo    = (const float*)d_in[5];
    const float* Wg    = (const float*)d_in[6];
    const float* Wn    = (const float*)d_in[7];
    float* out = (float*)d_out;

    const int gemm_smem = 6 * HGS * 2;                      // 110592
    const int attn_smem = (128 * HST + 6 * ATL) * 2;        // 73728
    cudaFuncSetAttribute(gemm_h, cudaFuncAttributeMaxDynamicSharedMemorySize, gemm_smem);
    cudaFuncSetAttribute(attn_h, cudaFuncAttributeMaxDynamicSharedMemorySize, attn_smem);

    zero_cnt<<<1, 32>>>();
    gate_kernel<<<NT, 256>>>(x, noise, Wg, Wn);
    prep_w<<<dim3(32, 32, 18), 256>>>(Wk, Wv, Wq, Wo);

    gemm_h<<<dim3(8, 32, 10), 128, gemm_smem>>>(0);    // k | v | q_sel (fused)

    transpose_v<<<dim3(32, 2, 64), 256>>>();

    attn_h<<<dim3(8, 16, 8), 256, attn_smem>>>();

    gemm_h<<<dim3(8, 32, 8), 128, gemm_smem>>>(2);     // o_sel

    combine<<<(NT * CC / 4) / 256, 256>>>(out);
}